// round 3
// baseline (speedup 1.0000x reference)
#include <cuda_runtime.h>
#include <cstdint>
#include <math.h>

// AFM: y[b] = fc_b + fc_w . sum_p softmax_p( w2 . relu(W1^T (x_i*x_j) + b1) ) * (x_i*x_j)
// One CTA per batch row. fp32 throughout; inner GEMV uses packed fma.rn.f32x2.

#define NF      32
#define EMB     64
#define NPAIR   496      // 32*31/2
#define XPAD    65       // pad X rows: stride-64 would be a 32-way bank conflict
#define THREADS 256

__device__ __forceinline__ void ffma2(uint64_t &acc, uint64_t a, uint64_t b) {
    asm("fma.rn.f32x2 %0, %1, %2, %0;" : "+l"(acc) : "l"(a), "l"(b));
}
__device__ __forceinline__ uint64_t bcast2(float v) {
    uint64_t r;
    asm("mov.b64 %0, {%1, %1};" : "=l"(r) : "r"(__float_as_uint(v)));
    return r;
}
__device__ __forceinline__ float lo32(uint64_t v) { return __uint_as_float((uint32_t)v); }
__device__ __forceinline__ float hi32(uint64_t v) { return __uint_as_float((uint32_t)(v >> 32)); }

__global__ __launch_bounds__(THREADS, 2)
void afm_kernel(const float* __restrict__ x,     // (B, 32, 64)
                const float* __restrict__ w1,    // (64, 64)  d-major rows
                const float* __restrict__ b1,    // (64)
                const float* __restrict__ w2,    // (64, 1)
                const float* __restrict__ fcw,   // (64, 1)
                const float* __restrict__ fcb,   // (1)
                float* __restrict__ out)         // (B, 1)
{
    __shared__ __align__(16) float Xs[NF * XPAD];
    __shared__ __align__(16) float W1s[EMB * EMB];
    __shared__ __align__(16) float b1s[EMB];
    __shared__ __align__(16) float w2s[EMB];
    __shared__ __align__(16) float fcws[EMB];
    __shared__ float score_s[NPAIR];
    __shared__ int   ci_s[NPAIR];
    __shared__ int   cj_s[NPAIR];
    __shared__ float fp_s[4 * EMB];
    __shared__ float red_s[8];
    __shared__ float smax_s, sinv_s;

    const int tid  = threadIdx.x;
    const int b    = blockIdx.x;
    const int lane = tid & 31;
    const int warp = tid >> 5;

    // ---- cooperative loads ----
    const float* xb = x + (size_t)b * (NF * EMB);
    for (int idx = tid; idx < NF * EMB; idx += THREADS)
        Xs[(idx >> 6) * XPAD + (idx & 63)] = xb[idx];   // coalesced read, padded store

    {
        const float4* w4  = (const float4*)w1;
        float4*       s4  = (float4*)W1s;
        for (int idx = tid; idx < (EMB * EMB) / 4; idx += THREADS) s4[idx] = w4[idx];
    }
    if (tid < EMB) { b1s[tid] = b1[tid]; w2s[tid] = w2[tid]; fcws[tid] = fcw[tid]; }

    // pair index tables (np.triu_indices(32, k=1) order)
    for (int p = tid; p < NPAIR; p += THREADS) {
        int i = 0, rem = p;
        while (rem >= NF - 1 - i) { rem -= NF - 1 - i; i++; }
        ci_s[p] = i;
        cj_s[p] = i + 1 + rem;
    }
    __syncthreads();

    // ---- phase 1: scores  score[p] = w2 . relu(W1^T c_p + b1),  c_p = x_i * x_j ----
    for (int p = tid; p < NPAIR; p += THREADS) {
        const float* xi = Xs + ci_s[p] * XPAD;
        const float* xj = Xs + cj_s[p] * XPAD;

        uint64_t acc[EMB / 2];                       // 32 packed f32x2 accumulators (a-dim)
        const uint64_t* b1p = (const uint64_t*)b1s;
        #pragma unroll
        for (int q = 0; q < EMB / 2; q++) acc[q] = b1p[q];

        #pragma unroll 4
        for (int d = 0; d < EMB; d++) {
            uint64_t cd2 = bcast2(xi[d] * xj[d]);
            const ulonglong2* wr = (const ulonglong2*)(W1s + d * EMB);  // broadcast LDS.128
            #pragma unroll
            for (int q = 0; q < EMB / 4; q++) {
                ulonglong2 w = wr[q];
                ffma2(acc[2 * q],     cd2, w.x);
                ffma2(acc[2 * q + 1], cd2, w.y);
            }
        }

        float s = 0.f;
        #pragma unroll
        for (int q = 0; q < EMB / 2; q++) {
            s += fmaxf(lo32(acc[q]), 0.f) * w2s[2 * q]
               + fmaxf(hi32(acc[q]), 0.f) * w2s[2 * q + 1];
        }
        score_s[p] = s;
    }
    __syncthreads();

    // ---- softmax over the 496 pairs ----
    // max
    float m = -INFINITY;
    for (int p = tid; p < NPAIR; p += THREADS) m = fmaxf(m, score_s[p]);
    #pragma unroll
    for (int o = 16; o; o >>= 1) m = fmaxf(m, __shfl_xor_sync(0xFFFFFFFFu, m, o));
    if (lane == 0) red_s[warp] = m;
    __syncthreads();
    if (tid == 0) {
        float mm = red_s[0];
        #pragma unroll
        for (int k = 1; k < 8; k++) mm = fmaxf(mm, red_s[k]);
        smax_s = mm;
    }
    __syncthreads();
    const float mm = smax_s;

    // exp + sum (each thread rewrites only its own entries)
    float lsum = 0.f;
    for (int p = tid; p < NPAIR; p += THREADS) {
        float e = expf(score_s[p] - mm);
        score_s[p] = e;
        lsum += e;
    }
    #pragma unroll
    for (int o = 16; o; o >>= 1) lsum += __shfl_xor_sync(0xFFFFFFFFu, lsum, o);
    if (lane == 0) red_s[warp] = lsum;
    __syncthreads();
    if (tid == 0) {
        float ss = 0.f;
        #pragma unroll
        for (int k = 0; k < 8; k++) ss += red_s[k];
        sinv_s = 1.0f / ss;
    }
    __syncthreads();
    const float inv = sinv_s;

    // ---- phase 2: f[d] = sum_p attn_p * x_i[d]*x_j[d], then y = f . fc_w + fc_b ----
    {
        const int d = tid & 63;        // lanes 0..63 -> dims (conflict-free via XPAD)
        const int c = tid >> 6;        // 4 pair-chunks
        float a = 0.f;
        for (int p = c; p < NPAIR; p += 4) {
            a += score_s[p] * Xs[ci_s[p] * XPAD + d] * Xs[cj_s[p] * XPAD + d];
        }
        fp_s[c * EMB + d] = a;
    }
    __syncthreads();
    if (tid < EMB) {
        float f = (fp_s[tid] + fp_s[EMB + tid] + fp_s[2 * EMB + tid] + fp_s[3 * EMB + tid]) * inv;
        fp_s[tid] = f * fcws[tid];
    }
    __syncthreads();
    if (tid == 0) {
        float y = fcb[0];
        #pragma unroll
        for (int k = 0; k < EMB; k++) y += fp_s[k];
        out[b] = y;
    }
}

extern "C" void kernel_launch(void* const* d_in, const int* in_sizes, int n_in,
                              void* d_out, int out_size)
{
    const float* x   = (const float*)d_in[0];
    const float* w1  = (const float*)d_in[1];
    const float* b1  = (const float*)d_in[2];
    const float* w2  = (const float*)d_in[3];
    const float* fcw = (const float*)d_in[4];
    const float* fcb = (const float*)d_in[5];
    float* out = (float*)d_out;

    const int batch = out_size;   // NUM_CLASSES = 1
    afm_kernel<<<batch, THREADS>>>(x, w1, b1, w2, fcw, fcb, out);
}

// round 5
// speedup vs baseline: 1.0006x; 1.0006x over previous
#include <cuda_runtime.h>
#include <cstdint>
#include <math.h>

// AFM: y[b] = fc_b + fc_w . sum_p softmax_p( w2 . relu(W1^T (x_i*x_j) + b1) ) * (x_i*x_j)
// One CTA per batch row. fp32 throughout; inner GEMV uses packed fma.rn.f32x2.

#define NF      32
#define EMB     64
#define NPAIR   496      // 32*31/2
#define XPAD    65       // pad X rows: stride-64 would be a 32-way bank conflict
#define THREADS 256

__device__ __forceinline__ void ffma2(uint64_t &acc, uint64_t a, uint64_t b) {
    asm("fma.rn.f32x2 %0, %1, %2, %0;" : "+l"(acc) : "l"(a), "l"(b));
}
__device__ __forceinline__ uint64_t bcast2(float v) {
    uint64_t r;
    asm("mov.b64 %0, {%1, %1};" : "=l"(r) : "r"(__float_as_uint(v)));
    return r;
}
__device__ __forceinline__ float lo32(uint64_t v) { return __uint_as_float((uint32_t)v); }
__device__ __forceinline__ float hi32(uint64_t v) { return __uint_as_float((uint32_t)(v >> 32)); }

__global__ __launch_bounds__(THREADS, 2)
void afm_kernel(const float* __restrict__ x,     // (B, 32, 64)
                const float* __restrict__ w1,    // (64, 64)  d-major rows
                const float* __restrict__ b1,    // (64)
                const float* __restrict__ w2,    // (64, 1)
                const float* __restrict__ fcw,   // (64, 1)
                const float* __restrict__ fcb,   // (1)
                float* __restrict__ out)         // (B, 1)
{
    __shared__ __align__(16) float Xs[NF * XPAD];
    __shared__ __align__(16) float W1s[EMB * EMB];
    __shared__ __align__(16) float b1s[EMB];
    __shared__ __align__(16) float w2s[EMB];
    __shared__ __align__(16) float fcws[EMB];
    __shared__ float score_s[NPAIR];
    __shared__ int   ci_s[NPAIR];
    __shared__ int   cj_s[NPAIR];
    __shared__ float fp_s[4 * EMB];
    __shared__ float red_s[8];
    __shared__ float smax_s, sinv_s;

    const int tid  = threadIdx.x;
    const int b    = blockIdx.x;
    const int lane = tid & 31;
    const int warp = tid >> 5;

    // ---- cooperative loads ----
    const float* xb = x + (size_t)b * (NF * EMB);
    for (int idx = tid; idx < NF * EMB; idx += THREADS)
        Xs[(idx >> 6) * XPAD + (idx & 63)] = xb[idx];   // coalesced read, padded store

    {
        const float4* w4  = (const float4*)w1;
        float4*       s4  = (float4*)W1s;
        for (int idx = tid; idx < (EMB * EMB) / 4; idx += THREADS) s4[idx] = w4[idx];
    }
    if (tid < EMB) { b1s[tid] = b1[tid]; w2s[tid] = w2[tid]; fcws[tid] = fcw[tid]; }

    // pair index tables (np.triu_indices(32, k=1) order)
    for (int p = tid; p < NPAIR; p += THREADS) {
        int i = 0, rem = p;
        while (rem >= NF - 1 - i) { rem -= NF - 1 - i; i++; }
        ci_s[p] = i;
        cj_s[p] = i + 1 + rem;
    }
    __syncthreads();

    // ---- phase 1: scores  score[p] = w2 . relu(W1^T c_p + b1),  c_p = x_i * x_j ----
    for (int p = tid; p < NPAIR; p += THREADS) {
        const float* xi = Xs + ci_s[p] * XPAD;
        const float* xj = Xs + cj_s[p] * XPAD;

        uint64_t acc[EMB / 2];                       // 32 packed f32x2 accumulators (a-dim)
        const uint64_t* b1p = (const uint64_t*)b1s;
        #pragma unroll
        for (int q = 0; q < EMB / 2; q++) acc[q] = b1p[q];

        #pragma unroll 4
        for (int d = 0; d < EMB; d++) {
            uint64_t cd2 = bcast2(xi[d] * xj[d]);
            const ulonglong2* wr = (const ulonglong2*)(W1s + d * EMB);  // broadcast LDS.128
            #pragma unroll
            for (int q = 0; q < EMB / 4; q++) {
                ulonglong2 w = wr[q];
                ffma2(acc[2 * q],     cd2, w.x);
                ffma2(acc[2 * q + 1], cd2, w.y);
            }
        }

        float s = 0.f;
        #pragma unroll
        for (int q = 0; q < EMB / 2; q++) {
            s += fmaxf(lo32(acc[q]), 0.f) * w2s[2 * q]
               + fmaxf(hi32(acc[q]), 0.f) * w2s[2 * q + 1];
        }
        score_s[p] = s;
    }
    __syncthreads();

    // ---- softmax over the 496 pairs ----
    // max
    float m = -INFINITY;
    for (int p = tid; p < NPAIR; p += THREADS) m = fmaxf(m, score_s[p]);
    #pragma unroll
    for (int o = 16; o; o >>= 1) m = fmaxf(m, __shfl_xor_sync(0xFFFFFFFFu, m, o));
    if (lane == 0) red_s[warp] = m;
    __syncthreads();
    if (tid == 0) {
        float mm = red_s[0];
        #pragma unroll
        for (int k = 1; k < 8; k++) mm = fmaxf(mm, red_s[k]);
        smax_s = mm;
    }
    __syncthreads();
    const float mm = smax_s;

    // exp + sum (each thread rewrites only its own entries)
    float lsum = 0.f;
    for (int p = tid; p < NPAIR; p += THREADS) {
        float e = expf(score_s[p] - mm);
        score_s[p] = e;
        lsum += e;
    }
    #pragma unroll
    for (int o = 16; o; o >>= 1) lsum += __shfl_xor_sync(0xFFFFFFFFu, lsum, o);
    if (lane == 0) red_s[warp] = lsum;
    __syncthreads();
    if (tid == 0) {
        float ss = 0.f;
        #pragma unroll
        for (int k = 0; k < 8; k++) ss += red_s[k];
        sinv_s = 1.0f / ss;
    }
    __syncthreads();
    const float inv = sinv_s;

    // ---- phase 2: f[d] = sum_p attn_p * x_i[d]*x_j[d], then y = f . fc_w + fc_b ----
    {
        const int d = tid & 63;        // lanes 0..63 -> dims (conflict-free via XPAD)
        const int c = tid >> 6;        // 4 pair-chunks
        float a = 0.f;
        for (int p = c; p < NPAIR; p += 4) {
            a += score_s[p] * Xs[ci_s[p] * XPAD + d] * Xs[cj_s[p] * XPAD + d];
        }
        fp_s[c * EMB + d] = a;
    }
    __syncthreads();
    if (tid < EMB) {
        float f = (fp_s[tid] + fp_s[EMB + tid] + fp_s[2 * EMB + tid] + fp_s[3 * EMB + tid]) * inv;
        fp_s[tid] = f * fcws[tid];
    }
    __syncthreads();
    if (tid == 0) {
        float y = fcb[0];
        #pragma unroll
        for (int k = 0; k < EMB; k++) y += fp_s[k];
        out[b] = y;
    }
}

extern "C" void kernel_launch(void* const* d_in, const int* in_sizes, int n_in,
                              void* d_out, int out_size)
{
    const float* x   = (const float*)d_in[0];
    const float* w1  = (const float*)d_in[1];
    const float* b1  = (const float*)d_in[2];
    const float* w2  = (const float*)d_in[3];
    const float* fcw = (const float*)d_in[4];
    const float* fcb = (const float*)d_in[5];
    float* out = (float*)d_out;

    const int batch = out_size;   // NUM_CLASSES = 1
    afm_kernel<<<batch, THREADS>>>(x, w1, b1, w2, fcw, fcb, out);
}

// round 6
// speedup vs baseline: 1.3422x; 1.3415x over previous
#include <cuda_runtime.h>
#include <cstdint>
#include <math.h>

// AFM: y[b] = fc_b + fc_w . sum_p softmax_p( w2 . relu(W1^T (x_i*x_j) + b1) ) * (x_i*x_j)
// One CTA per batch row. fp32; inner GEMV uses packed fma.rn.f32x2.
// R5: 2 pairs per thread (halves W1 LDS traffic per MAC), float4 x loads,
//     XPAD=68 for 16B alignment, single balanced pair pass, __expf.

#define NF      32
#define EMB     64
#define NPAIR   496      // 32*31/2
#define HPAIR   248      // pairs per half; thread t owns (t, t+248)
#define XPAD    68       // 16B-aligned rows, (68*i+d)%32 == (4i+d)%32: conflict-free for lane-varying d
#define THREADS 256

__device__ __forceinline__ void ffma2(uint64_t &acc, uint64_t a, uint64_t b) {
    asm("fma.rn.f32x2 %0, %1, %2, %0;" : "+l"(acc) : "l"(a), "l"(b));
}
__device__ __forceinline__ uint64_t bcast2(float v) {
    uint64_t r;
    asm("mov.b64 %0, {%1, %1};" : "=l"(r) : "r"(__float_as_uint(v)));
    return r;
}
__device__ __forceinline__ float lo32(uint64_t v) { return __uint_as_float((uint32_t)v); }
__device__ __forceinline__ float hi32(uint64_t v) { return __uint_as_float((uint32_t)(v >> 32)); }

__global__ __launch_bounds__(THREADS, 1)
void afm_kernel(const float* __restrict__ x,     // (B, 32, 64)
                const float* __restrict__ w1,    // (64, 64)  d-major rows
                const float* __restrict__ b1,    // (64)
                const float* __restrict__ w2,    // (64, 1)
                const float* __restrict__ fcw,   // (64, 1)
                const float* __restrict__ fcb,   // (1)
                float* __restrict__ out)         // (B, 1)
{
    __shared__ __align__(16) float Xs[NF * XPAD];
    __shared__ __align__(16) float W1s[EMB * EMB];
    __shared__ __align__(16) float b1s[EMB];
    __shared__ __align__(16) float w2s[EMB];
    __shared__ __align__(16) float fcws[EMB];
    __shared__ float score_s[NPAIR];
    __shared__ int   ci_s[NPAIR];
    __shared__ int   cj_s[NPAIR];
    __shared__ float fp_s[4 * EMB];
    __shared__ float red_s[8];
    __shared__ float smax_s, sinv_s;

    const int tid  = threadIdx.x;
    const int b    = blockIdx.x;
    const int lane = tid & 31;
    const int warp = tid >> 5;

    // ---- cooperative loads ----
    const float* xb = x + (size_t)b * (NF * EMB);
    for (int idx = tid; idx < NF * EMB; idx += THREADS)
        Xs[(idx >> 6) * XPAD + (idx & 63)] = xb[idx];   // coalesced read, padded store

    {
        const float4* w4  = (const float4*)w1;
        float4*       s4  = (float4*)W1s;
        for (int idx = tid; idx < (EMB * EMB) / 4; idx += THREADS) s4[idx] = w4[idx];
    }
    if (tid < EMB) { b1s[tid] = b1[tid]; w2s[tid] = w2[tid]; fcws[tid] = fcw[tid]; }

    // pair index tables (np.triu_indices(32, k=1) order)
    for (int p = tid; p < NPAIR; p += THREADS) {
        int i = 0, rem = p;
        while (rem >= NF - 1 - i) { rem -= NF - 1 - i; i++; }
        ci_s[p] = i;
        cj_s[p] = i + 1 + rem;
    }
    __syncthreads();

    // ---- phase 1: scores for 2 pairs per thread, W1 row loads shared ----
    if (tid < HPAIR) {
        const int pA = tid, pB = tid + HPAIR;
        const float* xiA = Xs + ci_s[pA] * XPAD;
        const float* xjA = Xs + cj_s[pA] * XPAD;
        const float* xiB = Xs + ci_s[pB] * XPAD;
        const float* xjB = Xs + cj_s[pB] * XPAD;

        uint64_t accA[EMB / 2], accB[EMB / 2];       // 2 x 32 packed f32x2 accumulators
        const uint64_t* b1p = (const uint64_t*)b1s;
        #pragma unroll
        for (int q = 0; q < EMB / 2; q++) { accA[q] = b1p[q]; accB[q] = b1p[q]; }

        for (int d4 = 0; d4 < EMB / 4; d4++) {       // rolled: keeps code in L0 I$
            float4 aI = *(const float4*)(xiA + 4 * d4);
            float4 aJ = *(const float4*)(xjA + 4 * d4);
            float4 bI = *(const float4*)(xiB + 4 * d4);
            float4 bJ = *(const float4*)(xjB + 4 * d4);
            uint64_t cA[4], cB[4];
            cA[0] = bcast2(aI.x * aJ.x); cA[1] = bcast2(aI.y * aJ.y);
            cA[2] = bcast2(aI.z * aJ.z); cA[3] = bcast2(aI.w * aJ.w);
            cB[0] = bcast2(bI.x * bJ.x); cB[1] = bcast2(bI.y * bJ.y);
            cB[2] = bcast2(bI.z * bJ.z); cB[3] = bcast2(bI.w * bJ.w);

            #pragma unroll
            for (int dd = 0; dd < 4; dd++) {
                const ulonglong2* wr = (const ulonglong2*)(W1s + (4 * d4 + dd) * EMB);
                #pragma unroll
                for (int q = 0; q < EMB / 4; q++) {  // 1 broadcast LDS.128 -> 4 FFMA2
                    ulonglong2 w = wr[q];
                    ffma2(accA[2 * q],     cA[dd], w.x);
                    ffma2(accA[2 * q + 1], cA[dd], w.y);
                    ffma2(accB[2 * q],     cB[dd], w.x);
                    ffma2(accB[2 * q + 1], cB[dd], w.y);
                }
            }
        }

        float sA = 0.f, sB = 0.f;
        #pragma unroll
        for (int q = 0; q < EMB / 2; q++) {
            sA += fmaxf(lo32(accA[q]), 0.f) * w2s[2 * q]
                + fmaxf(hi32(accA[q]), 0.f) * w2s[2 * q + 1];
            sB += fmaxf(lo32(accB[q]), 0.f) * w2s[2 * q]
                + fmaxf(hi32(accB[q]), 0.f) * w2s[2 * q + 1];
        }
        score_s[pA] = sA;
        score_s[pB] = sB;
    }
    __syncthreads();

    // ---- softmax over the 496 pairs ----
    float m = -INFINITY;
    for (int p = tid; p < NPAIR; p += THREADS) m = fmaxf(m, score_s[p]);
    #pragma unroll
    for (int o = 16; o; o >>= 1) m = fmaxf(m, __shfl_xor_sync(0xFFFFFFFFu, m, o));
    if (lane == 0) red_s[warp] = m;
    __syncthreads();
    if (tid == 0) {
        float mm = red_s[0];
        #pragma unroll
        for (int k = 1; k < 8; k++) mm = fmaxf(mm, red_s[k]);
        smax_s = mm;
    }
    __syncthreads();
    const float mm = smax_s;

    float lsum = 0.f;
    for (int p = tid; p < NPAIR; p += THREADS) {
        float e = __expf(score_s[p] - mm);
        score_s[p] = e;
        lsum += e;
    }
    #pragma unroll
    for (int o = 16; o; o >>= 1) lsum += __shfl_xor_sync(0xFFFFFFFFu, lsum, o);
    if (lane == 0) red_s[warp] = lsum;
    __syncthreads();
    if (tid == 0) {
        float ss = 0.f;
        #pragma unroll
        for (int k = 0; k < 8; k++) ss += red_s[k];
        sinv_s = 1.0f / ss;
    }
    __syncthreads();
    const float inv = sinv_s;

    // ---- phase 2: f[d] = sum_p attn_p * x_i[d]*x_j[d], then y = f . fc_w + fc_b ----
    {
        const int d = tid & 63;        // lanes -> dims: (4i + d)%32 conflict-free over lane-varying d
        const int c = tid >> 6;        // 4 pair-chunks
        float a = 0.f;
        for (int p = c; p < NPAIR; p += 4) {
            a += score_s[p] * Xs[ci_s[p] * XPAD + d] * Xs[cj_s[p] * XPAD + d];
        }
        fp_s[c * EMB + d] = a;
    }
    __syncthreads();
    if (tid < EMB) {
        float f = (fp_s[tid] + fp_s[EMB + tid] + fp_s[2 * EMB + tid] + fp_s[3 * EMB + tid]) * inv;
        fp_s[tid] = f * fcws[tid];
    }
    __syncthreads();
    if (tid == 0) {
        float y = fcb[0];
        #pragma unroll
        for (int k = 0; k < EMB; k++) y += fp_s[k];
        out[b] = y;
    }
}

extern "C" void kernel_launch(void* const* d_in, const int* in_sizes, int n_in,
                              void* d_out, int out_size)
{
    const float* x   = (const float*)d_in[0];
    const float* w1  = (const float*)d_in[1];
    const float* b1  = (const float*)d_in[2];
    const float* w2  = (const float*)d_in[3];
    const float* fcw = (const float*)d_in[4];
    const float* fcb = (const float*)d_in[5];
    float* out = (float*)d_out;

    const int batch = out_size;   // NUM_CLASSES = 1
    afm_kernel<<<batch, THREADS>>>(x, w1, b1, w2, fcw, fcb, out);
}

// round 7
// speedup vs baseline: 1.3945x; 1.0390x over previous
#include <cuda_runtime.h>
#include <cstdint>
#include <math.h>

// AFM: y[b] = fc_b + fc_w . sum_p softmax_p( w2 . relu(W1^T (x_i*x_j) + b1) ) * (x_i*x_j)
// One CTA per batch row.
// R7: materialize C[d][p] = x_i[d]*x_j[d] in smem (dynamic, 128KB), then score GEMM
//     as an 8-pair x 16-a register tile per thread -> 0.19 smem-floats per FMA,
//     moving the bottleneck from the L1 return bus to the FFMA2 pipe.

#define NF      32
#define EMB     64
#define NPAIR   496      // 32*31/2
#define XPAD    68       // 16B-aligned X rows
#define CS      500      // C row stride (floats); 500*4B = 2000B, 16B-aligned rows
#define THREADS 256
#define NGRP    62       // 496/8 pair-groups
#define ACH     4        // a-chunks of 16

struct Smem {
    float C[EMB * CS];            // 128000 B   C[d][p]
    float W1[EMB * EMB];          // 16384 B    W1[d][a]
    float Xs[NF * XPAD];          // 8704 B
    float score[NPAIR];           // 1984 B
    float sp[NPAIR * 4];          // 7936 B  per-(pair,achunk) partial scores
    int   ci[NPAIR];              // 1984 B
    int   cj[NPAIR];              // 1984 B
    float b1[EMB];
    float w2[EMB];
    float fcw[EMB];
    float fp[4 * EMB];
    float red[8];
    float smax, sinv;
};

__device__ __forceinline__ void ffma2(uint64_t &acc, uint64_t a, uint64_t b) {
    asm("fma.rn.f32x2 %0, %1, %2, %0;" : "+l"(acc) : "l"(a), "l"(b));
}
__device__ __forceinline__ uint64_t bcast2(float v) {
    uint64_t r;
    asm("mov.b64 %0, {%1, %1};" : "=l"(r) : "r"(__float_as_uint(v)));
    return r;
}
__device__ __forceinline__ float lo32(uint64_t v) { return __uint_as_float((uint32_t)v); }
__device__ __forceinline__ float hi32(uint64_t v) { return __uint_as_float((uint32_t)(v >> 32)); }

__global__ __launch_bounds__(THREADS, 1)
void afm_kernel(const float* __restrict__ x,     // (B, 32, 64)
                const float* __restrict__ w1,    // (64, 64)
                const float* __restrict__ b1,
                const float* __restrict__ w2,
                const float* __restrict__ fcw,
                const float* __restrict__ fcb,
                float* __restrict__ out)
{
    extern __shared__ __align__(16) char smem_raw[];
    Smem* S = (Smem*)smem_raw;

    const int tid  = threadIdx.x;
    const int b    = blockIdx.x;
    const int lane = tid & 31;
    const int warp = tid >> 5;

    // ---- cooperative loads ----
    const float* xb = x + (size_t)b * (NF * EMB);
    for (int idx = tid; idx < NF * EMB; idx += THREADS)
        S->Xs[(idx >> 6) * XPAD + (idx & 63)] = xb[idx];

    {
        const float4* w4 = (const float4*)w1;
        float4*       s4 = (float4*)S->W1;
        for (int idx = tid; idx < (EMB * EMB) / 4; idx += THREADS) s4[idx] = w4[idx];
    }
    if (tid < EMB) { S->b1[tid] = b1[tid]; S->w2[tid] = w2[tid]; S->fcw[tid] = fcw[tid]; }

    // pair tables (np.triu_indices(32, k=1))
    for (int p = tid; p < NPAIR; p += THREADS) {
        int i = 0, rem = p;
        while (rem >= NF - 1 - i) { rem -= NF - 1 - i; i++; }
        S->ci[p] = i;
        S->cj[p] = i + 1 + rem;
    }
    __syncthreads();

    // ---- phase A: build C[d][p] = x_i[d] * x_j[d] ----
    if (tid < 248) {
        #pragma unroll
        for (int h = 0; h < 2; h++) {
            int p = tid + h * 248;
            const float* xi = S->Xs + S->ci[p] * XPAD;
            const float* xj = S->Xs + S->cj[p] * XPAD;
            #pragma unroll 4
            for (int d4 = 0; d4 < EMB / 4; d4++) {
                float4 a = *(const float4*)(xi + 4 * d4);
                float4 c = *(const float4*)(xj + 4 * d4);
                S->C[(4 * d4 + 0) * CS + p] = a.x * c.x;   // lanes = consecutive p: conflict-free
                S->C[(4 * d4 + 1) * CS + p] = a.y * c.y;
                S->C[(4 * d4 + 2) * CS + p] = a.z * c.z;
                S->C[(4 * d4 + 3) * CS + p] = a.w * c.w;
            }
        }
    }
    __syncthreads();

    // ---- phase B: score GEMM. thread (g, ac): pairs 8g..8g+7, a-range 16ac..16ac+15 ----
    if (tid < NGRP * ACH) {
        const int g  = tid >> 2;
        const int ac = tid & 3;

        uint64_t acc[8][8];                       // [pair][a-f32x2]
        {
            const uint64_t* b1p = (const uint64_t*)(S->b1 + 16 * ac);
            #pragma unroll
            for (int p = 0; p < 8; p++)
                #pragma unroll
                for (int q = 0; q < 8; q++) acc[p][q] = b1p[q];
        }

        const float* Cbase = S->C + 8 * g;
        const float* Wbase = S->W1 + 16 * ac;

        #pragma unroll 2
        for (int d = 0; d < EMB; d++) {
            float4 c0 = *(const float4*)(Cbase + d * CS);
            float4 c1 = *(const float4*)(Cbase + d * CS + 4);
            uint64_t cb[8];
            cb[0] = bcast2(c0.x); cb[1] = bcast2(c0.y);
            cb[2] = bcast2(c0.z); cb[3] = bcast2(c0.w);
            cb[4] = bcast2(c1.x); cb[5] = bcast2(c1.y);
            cb[6] = bcast2(c1.z); cb[7] = bcast2(c1.w);

            const ulonglong2* wr = (const ulonglong2*)(Wbase + d * EMB);
            ulonglong2 wA = wr[0], wB = wr[1], wC = wr[2], wD = wr[3];
            uint64_t w[8] = { wA.x, wA.y, wB.x, wB.y, wC.x, wC.y, wD.x, wD.y };

            #pragma unroll
            for (int p = 0; p < 8; p++)
                #pragma unroll
                for (int q = 0; q < 8; q++)
                    ffma2(acc[p][q], cb[p], w[q]);
        }

        // partial score over this thread's 16 a-values
        #pragma unroll
        for (int p = 0; p < 8; p++) {
            float s = 0.f;
            #pragma unroll
            for (int q = 0; q < 8; q++) {
                s += fmaxf(lo32(acc[p][q]), 0.f) * S->w2[16 * ac + 2 * q]
                   + fmaxf(hi32(acc[p][q]), 0.f) * S->w2[16 * ac + 2 * q + 1];
            }
            S->sp[(8 * g + p) * 4 + ac] = s;
        }
    }
    __syncthreads();

    // combine a-chunk partials
    for (int p = tid; p < NPAIR; p += THREADS) {
        float4 v = *(const float4*)(S->sp + 4 * p);
        S->score[p] = v.x + v.y + v.z + v.w;
    }
    __syncthreads();

    // ---- softmax over 496 pairs ----
    float m = -INFINITY;
    for (int p = tid; p < NPAIR; p += THREADS) m = fmaxf(m, S->score[p]);
    #pragma unroll
    for (int o = 16; o; o >>= 1) m = fmaxf(m, __shfl_xor_sync(0xFFFFFFFFu, m, o));
    if (lane == 0) S->red[warp] = m;
    __syncthreads();
    if (tid == 0) {
        float mm = S->red[0];
        #pragma unroll
        for (int k = 1; k < 8; k++) mm = fmaxf(mm, S->red[k]);
        S->smax = mm;
    }
    __syncthreads();
    const float mm = S->smax;

    float lsum = 0.f;
    for (int p = tid; p < NPAIR; p += THREADS) {
        float e = __expf(S->score[p] - mm);
        S->score[p] = e;
        lsum += e;
    }
    #pragma unroll
    for (int o = 16; o; o >>= 1) lsum += __shfl_xor_sync(0xFFFFFFFFu, lsum, o);
    if (lane == 0) S->red[warp] = lsum;
    __syncthreads();
    if (tid == 0) {
        float ss = 0.f;
        #pragma unroll
        for (int k = 0; k < 8; k++) ss += S->red[k];
        S->sinv = 1.0f / ss;
    }
    __syncthreads();
    const float inv = S->sinv;

    // ---- phase 2: f[d] = sum_p attn_p * x_i[d]*x_j[d]; y = f.fc_w + fc_b ----
    {
        const int d = tid & 63;        // conflict-free over lane-varying d (XPAD=68)
        const int c = tid >> 6;
        float a = 0.f;
        for (int p = c; p < NPAIR; p += 4) {
            a += S->score[p] * S->Xs[S->ci[p] * XPAD + d] * S->Xs[S->cj[p] * XPAD + d];
        }
        S->fp[c * EMB + d] = a;
    }
    __syncthreads();
    if (tid < EMB) {
        float f = (S->fp[tid] + S->fp[EMB + tid] + S->fp[2 * EMB + tid] + S->fp[3 * EMB + tid]) * inv;
        S->fp[tid] = f * S->fcw[tid];
    }
    __syncthreads();
    if (tid == 0) {
        float y = fcb[0];
        #pragma unroll
        for (int k = 0; k < EMB; k++) y += S->fp[k];
        out[b] = y;
    }
}

extern "C" void kernel_launch(void* const* d_in, const int* in_sizes, int n_in,
                              void* d_out, int out_size)
{
    const float* x   = (const float*)d_in[0];
    const float* w1  = (const float*)d_in[1];
    const float* b1  = (const float*)d_in[2];
    const float* w2  = (const float*)d_in[3];
    const float* fcw = (const float*)d_in[4];
    const float* fcb = (const float*)d_in[5];
    float* out = (float*)d_out;

    static int smem_set = -1;
    const int smem_bytes = (int)sizeof(Smem);
    if (smem_set != smem_bytes) {   // idempotent host attribute set (not a stream op)
        cudaFuncSetAttribute(afm_kernel, cudaFuncAttributeMaxDynamicSharedMemorySize, smem_bytes);
        smem_set = smem_bytes;
    }

    const int batch = out_size;   // NUM_CLASSES = 1
    afm_kernel<<<batch, THREADS, smem_bytes>>>(x, w1, b1, w2, fcw, fcb, out);
}

// round 9
// speedup vs baseline: 1.5838x; 1.1357x over previous
#include <cuda_runtime.h>
#include <cuda_bf16.h>
#include <cstdint>
#include <math.h>

// AFM: y[b] = fc_b + fc_w . sum_p softmax_p( w2 . relu(W1^T (x_i*x_j) + b1) ) * (x_i*x_j)
// One CTA per batch row.
// R9: score GEMM on warp-level mma.sync m16n8k16 bf16 (sm_80+ PTX, compiles at
//     compute_100 unlike tcgen05) with split-bf16 compensation:
//     D = C_hi*W_hi + C_lo*W_hi + C_hi*W_lo  (lo*lo dropped, ~4e-6 rel).
//     512 padded pair-rows in 2 halves of 256; B fragments precomputed in smem.

#define NF      32
#define EMB     64
#define NPAIR   496
#define XPAD    68
#define THREADS 256
#define MH      256            // rows per half
#define ABYTES_ROW 272         // 136 bf16: 16B-aligned, 4-bank offset per row

struct Smem {
    char  A[MH * ABYTES_ROW];        // 69632  A half: [C_hi(cols 0-63) | C_lo(64-127)] bf16
    uint2 Bfrag[8][8][32];           // 16384  [src*4+ks][ntile][lane]: src0=W_hi, src1=W_lo
    float Xs[NF * XPAD];             // 8704
    float z[2 * EMB];                // (b1[a], w2[a]) interleaved
    float score[NPAIR];
    int   ci[NPAIR];
    int   cj[NPAIR];
    float fcw[EMB];
    float fp[4 * EMB];
    float red[8];
    float smax, sinv;
};

__device__ __forceinline__ uint32_t pack_bf16x2(__nv_bfloat16 l, __nv_bfloat16 h) {
    return (uint32_t)__bfloat16_as_ushort(l) | ((uint32_t)__bfloat16_as_ushort(h) << 16);
}

__device__ __forceinline__ void mma16816(float* d, const uint32_t* a, uint2 b) {
    asm volatile(
        "mma.sync.aligned.m16n8k16.row.col.f32.bf16.bf16.f32 "
        "{%0,%1,%2,%3}, {%4,%5,%6,%7}, {%8,%9}, {%0,%1,%2,%3};"
        : "+f"(d[0]), "+f"(d[1]), "+f"(d[2]), "+f"(d[3])
        : "r"(a[0]), "r"(a[1]), "r"(a[2]), "r"(a[3]), "r"(b.x), "r"(b.y));
}

__device__ __forceinline__ void lda(uint32_t* a, uint32_t Abase, int rbase, int k0, int lane) {
    int quad = lane >> 3, r8 = lane & 7;
    int row = rbase + r8 + ((quad & 1) << 3);
    int col = k0 + ((quad >> 1) << 3);
    uint32_t addr = Abase + (uint32_t)(row * ABYTES_ROW + col * 2);
    asm volatile("ldmatrix.sync.aligned.m8n8.x4.shared.b16 {%0,%1,%2,%3}, [%4];"
                 : "=r"(a[0]), "=r"(a[1]), "=r"(a[2]), "=r"(a[3]) : "r"(addr));
}

__global__ __launch_bounds__(THREADS)
void afm_kernel(const float* __restrict__ x,
                const float* __restrict__ w1,
                const float* __restrict__ b1,
                const float* __restrict__ w2,
                const float* __restrict__ fcw,
                const float* __restrict__ fcb,
                float* __restrict__ out)
{
    extern __shared__ __align__(16) char smem_raw[];
    Smem* S = (Smem*)smem_raw;
    uint32_t Abase;
    asm("{ .reg .u64 t; cvta.to.shared.u64 t, %1; cvt.u32.u64 %0, t; }"
        : "=r"(Abase) : "l"(S->A));

    const int tid  = threadIdx.x;
    const int b    = blockIdx.x;
    const int lane = tid & 31;
    const int warp = tid >> 5;

    // ---- cooperative loads ----
    const float* xb = x + (size_t)b * (NF * EMB);
    for (int idx = tid; idx < NF * EMB; idx += THREADS)
        S->Xs[(idx >> 6) * XPAD + (idx & 63)] = xb[idx];

    if (tid < EMB) {
        S->z[2 * tid] = b1[tid];
        S->z[2 * tid + 1] = w2[tid];
        S->fcw[tid] = fcw[tid];
    }

    for (int p = tid; p < NPAIR; p += THREADS) {
        int i = 0, rem = p;
        while (rem >= NF - 1 - i) { rem -= NF - 1 - i; i++; }
        S->ci[p] = i;
        S->cj[p] = i + 1 + rem;
    }

    // stage w1 into smem scratch (reusing A buffer) for the fragment build
    {
        float* Wtmp = (float*)S->A;
        for (int idx = tid; idx < EMB * EMB; idx += THREADS) Wtmp[idx] = w1[idx];
    }
    __syncthreads();

    // ---- build B fragments (once). src0 = W_hi, src1 = W_lo ----
    {
        const float* Wtmp = (const float*)S->A;
        for (int e = tid; e < 8 * 8 * 32; e += THREADS) {
            int ln = e & 31, n = (e >> 5) & 7, sk = e >> 8;   // sk = src*4 + ks4
            int src = sk >> 2, k4 = sk & 3;
            int c = ln & 3, g = ln >> 2;
            int a = n * 8 + g;
            int d0 = k4 * 16 + 2 * c;
            float f0 = Wtmp[(d0)     * EMB + a];
            float f1 = Wtmp[(d0 + 1) * EMB + a];
            float f2 = Wtmp[(d0 + 8) * EMB + a];
            float f3 = Wtmp[(d0 + 9) * EMB + a];
            __nv_bfloat16 h0 = __float2bfloat16_rn(f0), h1 = __float2bfloat16_rn(f1);
            __nv_bfloat16 h2 = __float2bfloat16_rn(f2), h3 = __float2bfloat16_rn(f3);
            __nv_bfloat16 v0, v1, v2, v3;
            if (src == 0) { v0 = h0; v1 = h1; v2 = h2; v3 = h3; }
            else {
                v0 = __float2bfloat16_rn(f0 - __bfloat162float(h0));
                v1 = __float2bfloat16_rn(f1 - __bfloat162float(h1));
                v2 = __float2bfloat16_rn(f2 - __bfloat162float(h2));
                v3 = __float2bfloat16_rn(f3 - __bfloat162float(h3));
            }
            S->Bfrag[sk][n][ln] = make_uint2(pack_bf16x2(v0, v1), pack_bf16x2(v2, v3));
        }
    }
    __syncthreads();

    // ---- two halves of 256 pair-rows ----
    for (int h = 0; h < 2; h++) {
        // build A half: row r, cols 0-63 = hi(C), 64-127 = lo(C)
        for (int idx = tid; idx < MH * 16; idx += THREADS) {
            int ch = idx & 15, r = idx >> 4;
            int p = h * MH + r;
            if (p < NPAIR) {
                const float* xi = S->Xs + S->ci[p] * XPAD + 4 * ch;
                const float* xj = S->Xs + S->cj[p] * XPAD + 4 * ch;
                float4 a4 = *(const float4*)xi;
                float4 c4 = *(const float4*)xj;
                float c0 = a4.x * c4.x, c1 = a4.y * c4.y, c2 = a4.z * c4.z, c3 = a4.w * c4.w;
                __nv_bfloat16 h0 = __float2bfloat16_rn(c0), h1 = __float2bfloat16_rn(c1);
                __nv_bfloat16 h2 = __float2bfloat16_rn(c2), h3 = __float2bfloat16_rn(c3);
                __nv_bfloat16 l0 = __float2bfloat16_rn(c0 - __bfloat162float(h0));
                __nv_bfloat16 l1 = __float2bfloat16_rn(c1 - __bfloat162float(h1));
                __nv_bfloat16 l2 = __float2bfloat16_rn(c2 - __bfloat162float(h2));
                __nv_bfloat16 l3 = __float2bfloat16_rn(c3 - __bfloat162float(h3));
                char* row = S->A + r * ABYTES_ROW;
                *(uint2*)(row + 8 * ch)       = make_uint2(pack_bf16x2(h0, h1), pack_bf16x2(h2, h3));
                *(uint2*)(row + 128 + 8 * ch) = make_uint2(pack_bf16x2(l0, l1), pack_bf16x2(l2, l3));
            } else if (h == 0 || idx < MH * 16) {
                // zero unused rows once so ldmatrix never sees stale bits patterns
                char* row = S->A + r * ABYTES_ROW;
                if (p >= NPAIR) {
                    *(uint2*)(row + 8 * ch)       = make_uint2(0u, 0u);
                    *(uint2*)(row + 128 + 8 * ch) = make_uint2(0u, 0u);
                }
            }
        }
        __syncthreads();

        // MMA: warp owns rows [32*warp, 32*warp+32) of this half = 2 m-tiles
        float d[2][8][4];
        #pragma unroll
        for (int mt = 0; mt < 2; mt++)
            #pragma unroll
            for (int n = 0; n < 8; n++)
                #pragma unroll
                for (int q = 0; q < 4; q++) d[mt][n][q] = 0.f;

        const int rb0 = warp * 32, rb1 = warp * 32 + 16;

        #pragma unroll
        for (int ks = 0; ks < 4; ks++) {             // A_hi x (W_hi + W_lo)
            uint32_t a0[4], a1[4];
            lda(a0, Abase, rb0, 16 * ks, lane);
            lda(a1, Abase, rb1, 16 * ks, lane);
            #pragma unroll
            for (int n = 0; n < 8; n++) {
                uint2 bh = S->Bfrag[ks][n][lane];
                uint2 bl = S->Bfrag[4 + ks][n][lane];
                mma16816(d[0][n], a0, bh);
                mma16816(d[0][n], a0, bl);
                mma16816(d[1][n], a1, bh);
                mma16816(d[1][n], a1, bl);
            }
        }
        #pragma unroll
        for (int ks = 0; ks < 4; ks++) {             // A_lo x W_hi
            uint32_t a0[4], a1[4];
            lda(a0, Abase, rb0, 64 + 16 * ks, lane);
            lda(a1, Abase, rb1, 64 + 16 * ks, lane);
            #pragma unroll
            for (int n = 0; n < 8; n++) {
                uint2 bh = S->Bfrag[ks][n][lane];
                mma16816(d[0][n], a0, bh);
                mma16816(d[1][n], a1, bh);
            }
        }

        // epilogue: score partials. thread covers rows {g, g+8} cols {8n+2c, +1}
        const int c = lane & 3, g = lane >> 2;
        float ps[2][2] = {{0.f, 0.f}, {0.f, 0.f}};
        #pragma unroll
        for (int mt = 0; mt < 2; mt++) {
            #pragma unroll
            for (int n = 0; n < 8; n++) {
                float4 zz = *(const float4*)&S->z[2 * (8 * n + 2 * c)];  // b1/w2 for 2 cols
                ps[mt][0] += fmaxf(d[mt][n][0] + zz.x, 0.f) * zz.y
                           + fmaxf(d[mt][n][1] + zz.z, 0.f) * zz.w;
                ps[mt][1] += fmaxf(d[mt][n][2] + zz.x, 0.f) * zz.y
                           + fmaxf(d[mt][n][3] + zz.z, 0.f) * zz.w;
            }
        }
        #pragma unroll
        for (int off = 1; off <= 2; off <<= 1) {
            ps[0][0] += __shfl_xor_sync(0xFFFFFFFFu, ps[0][0], off);
            ps[0][1] += __shfl_xor_sync(0xFFFFFFFFu, ps[0][1], off);
            ps[1][0] += __shfl_xor_sync(0xFFFFFFFFu, ps[1][0], off);
            ps[1][1] += __shfl_xor_sync(0xFFFFFFFFu, ps[1][1], off);
        }
        if (c == 0) {
            #pragma unroll
            for (int mt = 0; mt < 2; mt++) {
                int p0 = h * MH + warp * 32 + mt * 16 + g;
                if (p0 < NPAIR)     S->score[p0]     = ps[mt][0];
                if (p0 + 8 < NPAIR) S->score[p0 + 8] = ps[mt][1];
            }
        }
        __syncthreads();   // A consumed by all warps; safe to rebuild / proceed
    }

    // ---- softmax over 496 pairs ----
    float m = -INFINITY;
    for (int p = tid; p < NPAIR; p += THREADS) m = fmaxf(m, S->score[p]);
    #pragma unroll
    for (int o = 16; o; o >>= 1) m = fmaxf(m, __shfl_xor_sync(0xFFFFFFFFu, m, o));
    if (lane == 0) S->red[warp] = m;
    __syncthreads();
    if (tid == 0) {
        float mm = S->red[0];
        #pragma unroll
        for (int k = 1; k < 8; k++) mm = fmaxf(mm, S->red[k]);
        S->smax = mm;
    }
    __syncthreads();
    const float mm = S->smax;

    float lsum = 0.f;
    for (int p = tid; p < NPAIR; p += THREADS) {
        float e = __expf(S->score[p] - mm);
        S->score[p] = e;
        lsum += e;
    }
    #pragma unroll
    for (int o = 16; o; o >>= 1) lsum += __shfl_xor_sync(0xFFFFFFFFu, lsum, o);
    if (lane == 0) S->red[warp] = lsum;
    __syncthreads();
    if (tid == 0) {
        float ss = 0.f;
        #pragma unroll
        for (int k = 0; k < 8; k++) ss += S->red[k];
        S->sinv = 1.0f / ss;
    }
    __syncthreads();
    const float inv = S->sinv;

    // ---- phase 2: f[d] = sum_p attn_p * x_i[d]*x_j[d]; y = f.fc_w + fc_b ----
    {
        const int d = tid & 63;
        const int cch = tid >> 6;
        float a = 0.f;
        for (int p = cch; p < NPAIR; p += 4) {
            a += S->score[p] * S->Xs[S->ci[p] * XPAD + d] * S->Xs[S->cj[p] * XPAD + d];
        }
        S->fp[cch * EMB + d] = a;
    }
    __syncthreads();
    if (tid < EMB) {
        float f = (S->fp[tid] + S->fp[EMB + tid] + S->fp[2 * EMB + tid] + S->fp[3 * EMB + tid]) * inv;
        S->fp[tid] = f * S->fcw[tid];
    }
    __syncthreads();
    if (tid == 0) {
        float y = fcb[0];
        #pragma unroll
        for (int k = 0; k < EMB; k++) y += S->fp[k];
        out[b] = y;
    }
}

extern "C" void kernel_launch(void* const* d_in, const int* in_sizes, int n_in,
                              void* d_out, int out_size)
{
    const float* x   = (const float*)d_in[0];
    const float* w1  = (const float*)d_in[1];
    const float* b1  = (const float*)d_in[2];
    const float* w2  = (const float*)d_in[3];
    const float* fcw = (const float*)d_in[4];
    const float* fcb = (const float*)d_in[5];
    float* out = (float*)d_out;

    static int smem_set = -1;
    const int smem_bytes = (int)sizeof(Smem);
    if (smem_set != smem_bytes) {
        cudaFuncSetAttribute(afm_kernel, cudaFuncAttributeMaxDynamicSharedMemorySize, smem_bytes);
        smem_set = smem_bytes;
    }

    const int batch = out_size;   // NUM_CLASSES = 1
    afm_kernel<<<batch, THREADS, smem_bytes>>>(x, w1, b1, w2, fcw, fcb, out);
}

// round 10
// speedup vs baseline: 2.1939x; 1.3852x over previous
#include <cuda_runtime.h>
#include <cuda_bf16.h>
#include <cstdint>
#include <math.h>

// AFM: y[b] = fc_b + fc_w . sum_p softmax_p( w2 . relu(W1^T (x_i*x_j) + b1) ) * (x_i*x_j)
// One CTA per batch row.
// R10: R9 (mma.sync bf16 split-hi/lo) + 2 CTAs/SM residency:
//      __launch_bounds__(256,2) with the n-dim split into 2 groups of 4 tiles
//      (accumulators 64->32 floats) so the kernel fits 128 regs without spills.

#define NF      32
#define EMB     64
#define NPAIR   496
#define XPAD    68
#define THREADS 256
#define MH      256            // rows per half
#define ABYTES_ROW 272         // 136 bf16: 16B-aligned, 4-bank offset per row

struct Smem {
    char  A[MH * ABYTES_ROW];        // 69632  A half: [C_hi(cols 0-63) | C_lo(64-127)] bf16
    uint2 Bfrag[8][8][32];           // 16384  [src*4+ks][ntile][lane]: src0=W_hi, src1=W_lo
    float Xs[NF * XPAD];             // 8704
    float z[2 * EMB];                // (b1[a], w2[a]) interleaved
    float score[NPAIR];
    int   ci[NPAIR];
    int   cj[NPAIR];
    float fcw[EMB];
    float fp[4 * EMB];
    float red[8];
    float smax, sinv;
};

__device__ __forceinline__ uint32_t pack_bf16x2(__nv_bfloat16 l, __nv_bfloat16 h) {
    return (uint32_t)__bfloat16_as_ushort(l) | ((uint32_t)__bfloat16_as_ushort(h) << 16);
}

__device__ __forceinline__ void mma16816(float* d, const uint32_t* a, uint2 b) {
    asm volatile(
        "mma.sync.aligned.m16n8k16.row.col.f32.bf16.bf16.f32 "
        "{%0,%1,%2,%3}, {%4,%5,%6,%7}, {%8,%9}, {%0,%1,%2,%3};"
        : "+f"(d[0]), "+f"(d[1]), "+f"(d[2]), "+f"(d[3])
        : "r"(a[0]), "r"(a[1]), "r"(a[2]), "r"(a[3]), "r"(b.x), "r"(b.y));
}

__device__ __forceinline__ void lda(uint32_t* a, uint32_t Abase, int rbase, int k0, int lane) {
    int quad = lane >> 3, r8 = lane & 7;
    int row = rbase + r8 + ((quad & 1) << 3);
    int col = k0 + ((quad >> 1) << 3);
    uint32_t addr = Abase + (uint32_t)(row * ABYTES_ROW + col * 2);
    asm volatile("ldmatrix.sync.aligned.m8n8.x4.shared.b16 {%0,%1,%2,%3}, [%4];"
                 : "=r"(a[0]), "=r"(a[1]), "=r"(a[2]), "=r"(a[3]) : "r"(addr));
}

__global__ __launch_bounds__(THREADS, 2)
void afm_kernel(const float* __restrict__ x,
                const float* __restrict__ w1,
                const float* __restrict__ b1,
                const float* __restrict__ w2,
                const float* __restrict__ fcw,
                const float* __restrict__ fcb,
                float* __restrict__ out)
{
    extern __shared__ __align__(16) char smem_raw[];
    Smem* S = (Smem*)smem_raw;
    uint32_t Abase;
    asm("{ .reg .u64 t; cvta.to.shared.u64 t, %1; cvt.u32.u64 %0, t; }"
        : "=r"(Abase) : "l"(S->A));

    const int tid  = threadIdx.x;
    const int b    = blockIdx.x;
    const int lane = tid & 31;
    const int warp = tid >> 5;

    // ---- cooperative loads ----
    const float* xb = x + (size_t)b * (NF * EMB);
    for (int idx = tid; idx < NF * EMB; idx += THREADS)
        S->Xs[(idx >> 6) * XPAD + (idx & 63)] = xb[idx];

    if (tid < EMB) {
        S->z[2 * tid] = b1[tid];
        S->z[2 * tid + 1] = w2[tid];
        S->fcw[tid] = fcw[tid];
    }

    for (int p = tid; p < NPAIR; p += THREADS) {
        int i = 0, rem = p;
        while (rem >= NF - 1 - i) { rem -= NF - 1 - i; i++; }
        S->ci[p] = i;
        S->cj[p] = i + 1 + rem;
    }

    // stage w1 into smem scratch (reusing A buffer) for the fragment build
    {
        float* Wtmp = (float*)S->A;
        for (int idx = tid; idx < EMB * EMB; idx += THREADS) Wtmp[idx] = w1[idx];
    }
    __syncthreads();

    // ---- build B fragments (once). src0 = W_hi, src1 = W_lo ----
    {
        const float* Wtmp = (const float*)S->A;
        for (int e = tid; e < 8 * 8 * 32; e += THREADS) {
            int ln = e & 31, n = (e >> 5) & 7, sk = e >> 8;   // sk = src*4 + ks4
            int src = sk >> 2, k4 = sk & 3;
            int c = ln & 3, g = ln >> 2;
            int a = n * 8 + g;
            int d0 = k4 * 16 + 2 * c;
            float f0 = Wtmp[(d0)     * EMB + a];
            float f1 = Wtmp[(d0 + 1) * EMB + a];
            float f2 = Wtmp[(d0 + 8) * EMB + a];
            float f3 = Wtmp[(d0 + 9) * EMB + a];
            __nv_bfloat16 h0 = __float2bfloat16_rn(f0), h1 = __float2bfloat16_rn(f1);
            __nv_bfloat16 h2 = __float2bfloat16_rn(f2), h3 = __float2bfloat16_rn(f3);
            __nv_bfloat16 v0, v1, v2, v3;
            if (src == 0) { v0 = h0; v1 = h1; v2 = h2; v3 = h3; }
            else {
                v0 = __float2bfloat16_rn(f0 - __bfloat162float(h0));
                v1 = __float2bfloat16_rn(f1 - __bfloat162float(h1));
                v2 = __float2bfloat16_rn(f2 - __bfloat162float(h2));
                v3 = __float2bfloat16_rn(f3 - __bfloat162float(h3));
            }
            S->Bfrag[sk][n][ln] = make_uint2(pack_bf16x2(v0, v1), pack_bf16x2(v2, v3));
        }
    }
    __syncthreads();

    // ---- two halves of 256 pair-rows ----
    for (int h = 0; h < 2; h++) {
        // build A half: row r, cols 0-63 = hi(C), 64-127 = lo(C)
        for (int idx = tid; idx < MH * 16; idx += THREADS) {
            int ch = idx & 15, r = idx >> 4;
            int p = h * MH + r;
            if (p < NPAIR) {
                const float* xi = S->Xs + S->ci[p] * XPAD + 4 * ch;
                const float* xj = S->Xs + S->cj[p] * XPAD + 4 * ch;
                float4 a4 = *(const float4*)xi;
                float4 c4 = *(const float4*)xj;
                float c0 = a4.x * c4.x, c1 = a4.y * c4.y, c2 = a4.z * c4.z, c3 = a4.w * c4.w;
                __nv_bfloat16 h0 = __float2bfloat16_rn(c0), h1 = __float2bfloat16_rn(c1);
                __nv_bfloat16 h2 = __float2bfloat16_rn(c2), h3 = __float2bfloat16_rn(c3);
                __nv_bfloat16 l0 = __float2bfloat16_rn(c0 - __bfloat162float(h0));
                __nv_bfloat16 l1 = __float2bfloat16_rn(c1 - __bfloat162float(h1));
                __nv_bfloat16 l2 = __float2bfloat16_rn(c2 - __bfloat162float(h2));
                __nv_bfloat16 l3 = __float2bfloat16_rn(c3 - __bfloat162float(h3));
                char* row = S->A + r * ABYTES_ROW;
                *(uint2*)(row + 8 * ch)       = make_uint2(pack_bf16x2(h0, h1), pack_bf16x2(h2, h3));
                *(uint2*)(row + 128 + 8 * ch) = make_uint2(pack_bf16x2(l0, l1), pack_bf16x2(l2, l3));
            } else {
                char* row = S->A + r * ABYTES_ROW;
                *(uint2*)(row + 8 * ch)       = make_uint2(0u, 0u);
                *(uint2*)(row + 128 + 8 * ch) = make_uint2(0u, 0u);
            }
        }
        __syncthreads();

        // MMA: warp owns rows [32*warp, 32*warp+32) of this half = 2 m-tiles.
        // n split into 2 groups of 4 tiles to keep live regs under the 128 cap.
        const int rb0 = warp * 32, rb1 = warp * 32 + 16;
        const int c = lane & 3, g = lane >> 2;
        float ps[2][2] = {{0.f, 0.f}, {0.f, 0.f}};

        #pragma unroll
        for (int ng = 0; ng < 2; ng++) {
            float d[2][4][4];
            #pragma unroll
            for (int mt = 0; mt < 2; mt++)
                #pragma unroll
                for (int n4 = 0; n4 < 4; n4++)
                    #pragma unroll
                    for (int q = 0; q < 4; q++) d[mt][n4][q] = 0.f;

            #pragma unroll
            for (int ks = 0; ks < 4; ks++) {             // A_hi x (W_hi + W_lo)
                uint32_t a0[4], a1[4];
                lda(a0, Abase, rb0, 16 * ks, lane);
                lda(a1, Abase, rb1, 16 * ks, lane);
                #pragma unroll
                for (int n4 = 0; n4 < 4; n4++) {
                    int n = ng * 4 + n4;
                    uint2 bh = S->Bfrag[ks][n][lane];
                    uint2 bl = S->Bfrag[4 + ks][n][lane];
                    mma16816(d[0][n4], a0, bh);
                    mma16816(d[0][n4], a0, bl);
                    mma16816(d[1][n4], a1, bh);
                    mma16816(d[1][n4], a1, bl);
                }
            }
            #pragma unroll
            for (int ks = 0; ks < 4; ks++) {             // A_lo x W_hi
                uint32_t a0[4], a1[4];
                lda(a0, Abase, rb0, 64 + 16 * ks, lane);
                lda(a1, Abase, rb1, 64 + 16 * ks, lane);
                #pragma unroll
                for (int n4 = 0; n4 < 4; n4++) {
                    int n = ng * 4 + n4;
                    uint2 bh = S->Bfrag[ks][n][lane];
                    mma16816(d[0][n4], a0, bh);
                    mma16816(d[1][n4], a1, bh);
                }
            }

            // fold this n-group into the score partials
            #pragma unroll
            for (int mt = 0; mt < 2; mt++) {
                #pragma unroll
                for (int n4 = 0; n4 < 4; n4++) {
                    int n = ng * 4 + n4;
                    float4 zz = *(const float4*)&S->z[2 * (8 * n + 2 * c)];  // b1/w2 for 2 cols
                    ps[mt][0] += fmaxf(d[mt][n4][0] + zz.x, 0.f) * zz.y
                               + fmaxf(d[mt][n4][1] + zz.z, 0.f) * zz.w;
                    ps[mt][1] += fmaxf(d[mt][n4][2] + zz.x, 0.f) * zz.y
                               + fmaxf(d[mt][n4][3] + zz.z, 0.f) * zz.w;
                }
            }
        }

        #pragma unroll
        for (int off = 1; off <= 2; off <<= 1) {
            ps[0][0] += __shfl_xor_sync(0xFFFFFFFFu, ps[0][0], off);
            ps[0][1] += __shfl_xor_sync(0xFFFFFFFFu, ps[0][1], off);
            ps[1][0] += __shfl_xor_sync(0xFFFFFFFFu, ps[1][0], off);
            ps[1][1] += __shfl_xor_sync(0xFFFFFFFFu, ps[1][1], off);
        }
        if (c == 0) {
            #pragma unroll
            for (int mt = 0; mt < 2; mt++) {
                int p0 = h * MH + warp * 32 + mt * 16 + g;
                if (p0 < NPAIR)     S->score[p0]     = ps[mt][0];
                if (p0 + 8 < NPAIR) S->score[p0 + 8] = ps[mt][1];
            }
        }
        __syncthreads();   // A consumed by all warps; safe to rebuild / proceed
    }

    // ---- softmax over 496 pairs ----
    float m = -INFINITY;
    for (int p = tid; p < NPAIR; p += THREADS) m = fmaxf(m, S->score[p]);
    #pragma unroll
    for (int o = 16; o; o >>= 1) m = fmaxf(m, __shfl_xor_sync(0xFFFFFFFFu, m, o));
    if (lane == 0) S->red[warp] = m;
    __syncthreads();
    if (tid == 0) {
        float mm = S->red[0];
        #pragma unroll
        for (int k = 1; k < 8; k++) mm = fmaxf(mm, S->red[k]);
        S->smax = mm;
    }
    __syncthreads();
    const float mm = S->smax;

    float lsum = 0.f;
    for (int p = tid; p < NPAIR; p += THREADS) {
        float e = __expf(S->score[p] - mm);
        S->score[p] = e;
        lsum += e;
    }
    #pragma unroll
    for (int o = 16; o; o >>= 1) lsum += __shfl_xor_sync(0xFFFFFFFFu, lsum, o);
    if (lane == 0) S->red[warp] = lsum;
    __syncthreads();
    if (tid == 0) {
        float ss = 0.f;
        #pragma unroll
        for (int k = 0; k < 8; k++) ss += S->red[k];
        S->sinv = 1.0f / ss;
    }
    __syncthreads();
    const float inv = S->sinv;

    // ---- phase 2: f[d] = sum_p attn_p * x_i[d]*x_j[d]; y = f.fc_w + fc_b ----
    {
        const int d = tid & 63;
        const int cch = tid >> 6;
        float a = 0.f;
        for (int p = cch; p < NPAIR; p += 4) {
            a += S->score[p] * S->Xs[S->ci[p] * XPAD + d] * S->Xs[S->cj[p] * XPAD + d];
        }
        S->fp[cch * EMB + d] = a;
    }
    __syncthreads();
    if (tid < EMB) {
        float f = (S->fp[tid] + S->fp[EMB + tid] + S->fp[2 * EMB + tid] + S->fp[3 * EMB + tid]) * inv;
        S->fp[tid] = f * S->fcw[tid];
    }
    __syncthreads();
    if (tid == 0) {
        float y = fcb[0];
        #pragma unroll
        for (int k = 0; k < EMB; k++) y += S->fp[k];
        out[b] = y;
    }
}

extern "C" void kernel_launch(void* const* d_in, const int* in_sizes, int n_in,
                              void* d_out, int out_size)
{
    const float* x   = (const float*)d_in[0];
    const float* w1  = (const float*)d_in[1];
    const float* b1  = (const float*)d_in[2];
    const float* w2  = (const float*)d_in[3];
    const float* fcw = (const float*)d_in[4];
    const float* fcb = (const float*)d_in[5];
    float* out = (float*)d_out;

    static int smem_set = -1;
    const int smem_bytes = (int)sizeof(Smem);
    if (smem_set != smem_bytes) {
        cudaFuncSetAttribute(afm_kernel, cudaFuncAttributeMaxDynamicSharedMemorySize, smem_bytes);
        smem_set = smem_bytes;
    }

    const int batch = out_size;   // NUM_CLASSES = 1
    afm_kernel<<<batch, THREADS, smem_bytes>>>(x, w1, b1, w2, fcw, fcb, out);
}

// round 11
// speedup vs baseline: 2.6851x; 1.2239x over previous
#include <cuda_runtime.h>
#include <cuda_bf16.h>
#include <cstdint>
#include <math.h>

// AFM: y[b] = fc_b + fc_w . sum_p softmax_p( w2 . relu(W1^T (x_i*x_j) + b1) ) * (x_i*x_j)
// One CTA per batch row.
// R11: R10 (mma.sync bf16 split-hi/lo) with 3 CTAs/SM:
//      A buffer quartered (MH=128, smem ~69KB), launch_bounds(256,3) (<=85 regs),
//      phase-2 vectorized (float4 + packed pair offsets), closed-form triu index.

#define NF      32
#define EMB     64
#define NPAIR   496
#define XPAD    68
#define THREADS 256
#define MH      128            // rows per quarter
#define NQ      4
#define ABYTES_ROW 272         // 136 bf16: 16B-aligned, 4-bank offset per row

struct Smem {
    char  A[MH * ABYTES_ROW];        // 34816  A quarter: [C_hi(0-63) | C_lo(64-127)] bf16
    uint2 Bfrag[8][8][32];           // 16384  [src*4+ks][ntile][lane]: src0=W_hi, src1=W_lo
    float Xs[NF * XPAD];             // 8704
    float z[2 * EMB];                // (b1[a], w2[a]) interleaved
    float score[NPAIR];              // 1984
    uint32_t offs[NPAIR];            // 1984   (ci*XPAD) | (cj*XPAD)<<16  (word offsets)
    float fcw[EMB];
    float fp[16 * EMB];              // 4096   phase-2 partials
    float red[8];
    float smax, sinv;
};

__device__ __forceinline__ uint32_t pack_bf16x2(__nv_bfloat16 l, __nv_bfloat16 h) {
    return (uint32_t)__bfloat16_as_ushort(l) | ((uint32_t)__bfloat16_as_ushort(h) << 16);
}

__device__ __forceinline__ void mma16816(float* d, const uint32_t* a, uint2 b) {
    asm volatile(
        "mma.sync.aligned.m16n8k16.row.col.f32.bf16.bf16.f32 "
        "{%0,%1,%2,%3}, {%4,%5,%6,%7}, {%8,%9}, {%0,%1,%2,%3};"
        : "+f"(d[0]), "+f"(d[1]), "+f"(d[2]), "+f"(d[3])
        : "r"(a[0]), "r"(a[1]), "r"(a[2]), "r"(a[3]), "r"(b.x), "r"(b.y));
}

// A fragment for one 16x16 tile at (rbase, k0)
__device__ __forceinline__ void lda(uint32_t* a, uint32_t Abase, int rbase, int k0, int lane) {
    int mat = lane >> 3, r8 = lane & 7;
    int row = rbase + r8 + ((mat & 1) << 3);
    int col = k0 + ((mat >> 1) << 3);
    uint32_t addr = Abase + (uint32_t)(row * ABYTES_ROW + col * 2);
    asm volatile("ldmatrix.sync.aligned.m8n8.x4.shared.b16 {%0,%1,%2,%3}, [%4];"
                 : "=r"(a[0]), "=r"(a[1]), "=r"(a[2]), "=r"(a[3]) : "r"(addr));
}

__global__ __launch_bounds__(THREADS, 3)
void afm_kernel(const float* __restrict__ x,
                const float* __restrict__ w1,
                const float* __restrict__ b1,
                const float* __restrict__ w2,
                const float* __restrict__ fcw,
                const float* __restrict__ fcb,
                float* __restrict__ out)
{
    extern __shared__ __align__(16) char smem_raw[];
    Smem* S = (Smem*)smem_raw;
    uint32_t Abase;
    asm("{ .reg .u64 t; cvta.to.shared.u64 t, %1; cvt.u32.u64 %0, t; }"
        : "=r"(Abase) : "l"(S->A));

    const int tid  = threadIdx.x;
    const int b    = blockIdx.x;
    const int lane = tid & 31;
    const int warp = tid >> 5;

    // ---- cooperative loads ----
    const float* xb = x + (size_t)b * (NF * EMB);
    for (int idx = tid; idx < NF * EMB; idx += THREADS)
        S->Xs[(idx >> 6) * XPAD + (idx & 63)] = xb[idx];

    if (tid < EMB) {
        S->z[2 * tid] = b1[tid];
        S->z[2 * tid + 1] = w2[tid];
        S->fcw[tid] = fcw[tid];
    }

    // pair offsets via closed-form triu index: row i starts at i*(63-i)/2
    for (int p = tid; p < NPAIR; p += THREADS) {
        float t = sqrtf((float)(3969 - 8 * p));
        int i = (int)((63.0f - t) * 0.5f);
        while ((i + 1) * (63 - (i + 1)) / 2 <= p) i++;   // <=2 fixup steps
        while (i * (63 - i) / 2 > p) i--;
        int j = i + 1 + (p - i * (63 - i) / 2);
        S->offs[p] = (uint32_t)(i * XPAD) | ((uint32_t)(j * XPAD) << 16);
    }

    // stage w1 into smem scratch (reusing A buffer) for the fragment build
    {
        float* Wtmp = (float*)S->A;
        for (int idx = tid; idx < EMB * EMB; idx += THREADS) Wtmp[idx] = w1[idx];
    }
    __syncthreads();

    // ---- build B fragments (once). src0 = W_hi, src1 = W_lo ----
    {
        const float* Wtmp = (const float*)S->A;
        for (int e = tid; e < 8 * 8 * 32; e += THREADS) {
            int ln = e & 31, n = (e >> 5) & 7, sk = e >> 8;   // sk = src*4 + ks4
            int src = sk >> 2, k4 = sk & 3;
            int c = ln & 3, g = ln >> 2;
            int a = n * 8 + g;
            int d0 = k4 * 16 + 2 * c;
            float f0 = Wtmp[(d0)     * EMB + a];
            float f1 = Wtmp[(d0 + 1) * EMB + a];
            float f2 = Wtmp[(d0 + 8) * EMB + a];
            float f3 = Wtmp[(d0 + 9) * EMB + a];
            __nv_bfloat16 h0 = __float2bfloat16_rn(f0), h1 = __float2bfloat16_rn(f1);
            __nv_bfloat16 h2 = __float2bfloat16_rn(f2), h3 = __float2bfloat16_rn(f3);
            __nv_bfloat16 v0, v1, v2, v3;
            if (src == 0) { v0 = h0; v1 = h1; v2 = h2; v3 = h3; }
            else {
                v0 = __float2bfloat16_rn(f0 - __bfloat162float(h0));
                v1 = __float2bfloat16_rn(f1 - __bfloat162float(h1));
                v2 = __float2bfloat16_rn(f2 - __bfloat162float(h2));
                v3 = __float2bfloat16_rn(f3 - __bfloat162float(h3));
            }
            S->Bfrag[sk][n][ln] = make_uint2(pack_bf16x2(v0, v1), pack_bf16x2(v2, v3));
        }
    }
    __syncthreads();

    // ---- four quarters of 128 pair-rows ----
    for (int qt = 0; qt < NQ; qt++) {
        // build A quarter: row r, cols 0-63 = hi(C), 64-127 = lo(C)
        for (int idx = tid; idx < MH * 16; idx += THREADS) {
            int ch = idx & 15, r = idx >> 4;
            int p = qt * MH + r;
            char* row = S->A + r * ABYTES_ROW;
            if (p < NPAIR) {
                uint32_t o = S->offs[p];
                const float* xi = S->Xs + (o & 0xFFFFu) + 4 * ch;
                const float* xj = S->Xs + (o >> 16) + 4 * ch;
                float4 a4 = *(const float4*)xi;
                float4 c4 = *(const float4*)xj;
                float c0 = a4.x * c4.x, c1 = a4.y * c4.y, c2 = a4.z * c4.z, c3 = a4.w * c4.w;
                __nv_bfloat16 h0 = __float2bfloat16_rn(c0), h1 = __float2bfloat16_rn(c1);
                __nv_bfloat16 h2 = __float2bfloat16_rn(c2), h3 = __float2bfloat16_rn(c3);
                __nv_bfloat16 l0 = __float2bfloat16_rn(c0 - __bfloat162float(h0));
                __nv_bfloat16 l1 = __float2bfloat16_rn(c1 - __bfloat162float(h1));
                __nv_bfloat16 l2 = __float2bfloat16_rn(c2 - __bfloat162float(h2));
                __nv_bfloat16 l3 = __float2bfloat16_rn(c3 - __bfloat162float(h3));
                *(uint2*)(row + 8 * ch)       = make_uint2(pack_bf16x2(h0, h1), pack_bf16x2(h2, h3));
                *(uint2*)(row + 128 + 8 * ch) = make_uint2(pack_bf16x2(l0, l1), pack_bf16x2(l2, l3));
            } else {
                *(uint2*)(row + 8 * ch)       = make_uint2(0u, 0u);
                *(uint2*)(row + 128 + 8 * ch) = make_uint2(0u, 0u);
            }
        }
        __syncthreads();

        // MMA: warp owns one 16-row m-tile: rows [16*warp, 16*warp+16)
        const int rb = warp * 16;
        const int c = lane & 3, g = lane >> 2;
        float ps0 = 0.f, ps1 = 0.f;

        #pragma unroll
        for (int ng = 0; ng < 2; ng++) {
            float d[4][4];
            #pragma unroll
            for (int n4 = 0; n4 < 4; n4++)
                #pragma unroll
                for (int q = 0; q < 4; q++) d[n4][q] = 0.f;

            #pragma unroll
            for (int ks = 0; ks < 4; ks++) {             // A_hi x (W_hi + W_lo)
                uint32_t a[4];
                lda(a, Abase, rb, 16 * ks, lane);
                #pragma unroll
                for (int n4 = 0; n4 < 4; n4++) {
                    int n = ng * 4 + n4;
                    uint2 bh = S->Bfrag[ks][n][lane];
                    uint2 bl = S->Bfrag[4 + ks][n][lane];
                    mma16816(d[n4], a, bh);
                    mma16816(d[n4], a, bl);
                }
            }
            #pragma unroll
            for (int ks = 0; ks < 4; ks++) {             // A_lo x W_hi
                uint32_t a[4];
                lda(a, Abase, rb, 64 + 16 * ks, lane);
                #pragma unroll
                for (int n4 = 0; n4 < 4; n4++) {
                    uint2 bh = S->Bfrag[ks][ng * 4 + n4][lane];
                    mma16816(d[n4], a, bh);
                }
            }

            // fold this n-group into partial scores
            #pragma unroll
            for (int n4 = 0; n4 < 4; n4++) {
                int n = ng * 4 + n4;
                float4 zz = *(const float4*)&S->z[2 * (8 * n + 2 * c)];  // b1/w2 for 2 cols
                ps0 += fmaxf(d[n4][0] + zz.x, 0.f) * zz.y
                     + fmaxf(d[n4][1] + zz.z, 0.f) * zz.w;
                ps1 += fmaxf(d[n4][2] + zz.x, 0.f) * zz.y
                     + fmaxf(d[n4][3] + zz.z, 0.f) * zz.w;
            }
        }

        #pragma unroll
        for (int off = 1; off <= 2; off <<= 1) {
            ps0 += __shfl_xor_sync(0xFFFFFFFFu, ps0, off);
            ps1 += __shfl_xor_sync(0xFFFFFFFFu, ps1, off);
        }
        if (c == 0) {
            int p0 = qt * MH + rb + g;
            if (p0 < NPAIR)     S->score[p0]     = ps0;
            if (p0 + 8 < NPAIR) S->score[p0 + 8] = ps1;
        }
        __syncthreads();   // A consumed by all warps; safe to rebuild
    }

    // ---- softmax over 496 pairs ----
    float m = -INFINITY;
    for (int p = tid; p < NPAIR; p += THREADS) m = fmaxf(m, S->score[p]);
    #pragma unroll
    for (int o = 16; o; o >>= 1) m = fmaxf(m, __shfl_xor_sync(0xFFFFFFFFu, m, o));
    if (lane == 0) S->red[warp] = m;
    __syncthreads();
    if (tid == 0) {
        float mm = S->red[0];
        #pragma unroll
        for (int k = 1; k < 8; k++) mm = fmaxf(mm, S->red[k]);
        S->smax = mm;
    }
    __syncthreads();
    const float mm = S->smax;

    float lsum = 0.f;
    for (int p = tid; p < NPAIR; p += THREADS) {
        float e = __expf(S->score[p] - mm);
        S->score[p] = e;
        lsum += e;
    }
    #pragma unroll
    for (int o = 16; o; o >>= 1) lsum += __shfl_xor_sync(0xFFFFFFFFu, lsum, o);
    if (lane == 0) S->red[warp] = lsum;
    __syncthreads();
    if (tid == 0) {
        float ss = 0.f;
        #pragma unroll
        for (int k = 0; k < 8; k++) ss += S->red[k];
        S->sinv = 1.0f / ss;
    }
    __syncthreads();
    const float inv = S->sinv;

    // ---- phase 2: f[d] = sum_p attn_p * x_i[d]*x_j[d]; y = f.fc_w + fc_b ----
    {
        const int dg = tid & 15;        // dim group: dims [4dg, 4dg+4)
        const int pg = tid >> 4;        // 16 pair groups
        float4 acc = make_float4(0.f, 0.f, 0.f, 0.f);
        for (int p = pg; p < NPAIR; p += 16) {
            float s = S->score[p];
            uint32_t o = S->offs[p];
            float4 xi = *(const float4*)(S->Xs + (o & 0xFFFFu) + 4 * dg);
            float4 xj = *(const float4*)(S->Xs + (o >> 16) + 4 * dg);
            acc.x += s * (xi.x * xj.x);
            acc.y += s * (xi.y * xj.y);
            acc.z += s * (xi.z * xj.z);
            acc.w += s * (xi.w * xj.w);
        }
        *(float4*)(S->fp + pg * EMB + 4 * dg) = acc;
    }
    __syncthreads();
    if (tid < EMB) {
        float f = 0.f;
        #pragma unroll
        for (int pg = 0; pg < 16; pg++) f += S->fp[pg * EMB + tid];
        S->fp[tid] = f * inv * S->fcw[tid];
    }
    __syncthreads();
    if (tid == 0) {
        float y = fcb[0];
        #pragma unroll
        for (int k = 0; k < EMB; k++) y += S->fp[k];
        out[b] = y;
    }
}

extern "C" void kernel_launch(void* const* d_in, const int* in_sizes, int n_in,
                              void* d_out, int out_size)
{
    const float* x   = (const float*)d_in[0];
    const float* w1  = (const float*)d_in[1];
    const float* b1  = (const float*)d_in[2];
    const float* w2  = (const float*)d_in[3];
    const float* fcw = (const float*)d_in[4];
    const float* fcb = (const float*)d_in[5];
    float* out = (float*)d_out;

    static int smem_set = -1;
    const int smem_bytes = (int)sizeof(Smem);
    if (smem_set != smem_bytes) {
        cudaFuncSetAttribute(afm_kernel, cudaFuncAttributeMaxDynamicSharedMemorySize, smem_bytes);
        smem_set = smem_bytes;
    }

    const int batch = out_size;   // NUM_CLASSES = 1
    afm_kernel<<<batch, THREADS, smem_bytes>>>(x, w1, b1, w2, fcw, fcb, out);
}

// round 12
// speedup vs baseline: 3.1941x; 1.1896x over previous
#include <cuda_runtime.h>
#include <cuda_bf16.h>
#include <cstdint>
#include <math.h>

// AFM: y[b] = fc_b + fc_w . sum_p softmax_p( w2 . relu(W1^T (x_i*x_j) + b1) ) * (x_i*x_j)
// One CTA per batch row.
// R12: R11 + L1-wavefront diet:
//   - Bfrag built once chip-wide by a prep kernel into __device__ global; main
//     kernel just copies 16KB to smem (kills per-CTA w1 staging + build).
//   - MMA loop restructured: per (ng,ks) load a_hi+a_lo, per n4 load bh+bl once
//     and issue all 3 MMAs -> Bfrag smem loads 96->64 per warp-quarter.
//   - buildA uses packed cvt.rn.bf16x2.f32 conversions.

#define NF      32
#define EMB     64
#define NPAIR   496
#define XPAD    68
#define THREADS 256
#define MH      128            // rows per quarter
#define NQ      4
#define ABYTES_ROW 272         // 136 bf16: 16B-aligned, 4-bank offset per row

__device__ uint2 g_Bfrag[8][8][32];   // [src*4+ks][ntile][lane]; src0=W_hi, src1=W_lo

struct Smem {
    char  A[MH * ABYTES_ROW];        // 34816  A quarter: [C_hi(0-63) | C_lo(64-127)] bf16
    uint2 Bfrag[8][8][32];           // 16384
    float Xs[NF * XPAD];             // 8704
    float z[2 * EMB];                // (b1[a], w2[a]) interleaved
    float score[NPAIR];              // 1984
    uint32_t offs[NPAIR];            // 1984   (ci*XPAD) | (cj*XPAD)<<16  (word offsets)
    float fcw[EMB];
    float fp[16 * EMB];              // 4096   phase-2 partials
    float red[8];
    float smax, sinv;
};

__device__ __forceinline__ uint32_t pack_bf16x2(__nv_bfloat16 l, __nv_bfloat16 h) {
    return (uint32_t)__bfloat16_as_ushort(l) | ((uint32_t)__bfloat16_as_ushort(h) << 16);
}

// packed pair (lo=a, hi=b) -> bf16x2 in one cvt
__device__ __forceinline__ uint32_t cvt2_bf16(float lo, float hi) {
    uint32_t r;
    asm("cvt.rn.bf16x2.f32 %0, %1, %2;" : "=r"(r) : "f"(hi), "f"(lo));
    return r;
}

__device__ __forceinline__ void mma16816(float* d, const uint32_t* a, uint2 b) {
    asm volatile(
        "mma.sync.aligned.m16n8k16.row.col.f32.bf16.bf16.f32 "
        "{%0,%1,%2,%3}, {%4,%5,%6,%7}, {%8,%9}, {%0,%1,%2,%3};"
        : "+f"(d[0]), "+f"(d[1]), "+f"(d[2]), "+f"(d[3])
        : "r"(a[0]), "r"(a[1]), "r"(a[2]), "r"(a[3]), "r"(b.x), "r"(b.y));
}

__device__ __forceinline__ void lda(uint32_t* a, uint32_t Abase, int rbase, int k0, int lane) {
    int mat = lane >> 3, r8 = lane & 7;
    int row = rbase + r8 + ((mat & 1) << 3);
    int col = k0 + ((mat >> 1) << 3);
    uint32_t addr = Abase + (uint32_t)(row * ABYTES_ROW + col * 2);
    asm volatile("ldmatrix.sync.aligned.m8n8.x4.shared.b16 {%0,%1,%2,%3}, [%4];"
                 : "=r"(a[0]), "=r"(a[1]), "=r"(a[2]), "=r"(a[3]) : "r"(addr));
}

// ---- one-time chip-wide B-fragment build (batch-invariant) ----
__global__ void bfrag_prep(const float* __restrict__ w1) {
    int tid = threadIdx.x;
    for (int e = tid; e < 8 * 8 * 32; e += 256) {
        int ln = e & 31, n = (e >> 5) & 7, sk = e >> 8;   // sk = src*4 + ks4
        int src = sk >> 2, k4 = sk & 3;
        int c = ln & 3, g = ln >> 2;
        int a = n * 8 + g;
        int d0 = k4 * 16 + 2 * c;
        float f0 = w1[(d0)     * EMB + a];
        float f1 = w1[(d0 + 1) * EMB + a];
        float f2 = w1[(d0 + 8) * EMB + a];
        float f3 = w1[(d0 + 9) * EMB + a];
        __nv_bfloat16 h0 = __float2bfloat16_rn(f0), h1 = __float2bfloat16_rn(f1);
        __nv_bfloat16 h2 = __float2bfloat16_rn(f2), h3 = __float2bfloat16_rn(f3);
        __nv_bfloat16 v0, v1, v2, v3;
        if (src == 0) { v0 = h0; v1 = h1; v2 = h2; v3 = h3; }
        else {
            v0 = __float2bfloat16_rn(f0 - __bfloat162float(h0));
            v1 = __float2bfloat16_rn(f1 - __bfloat162float(h1));
            v2 = __float2bfloat16_rn(f2 - __bfloat162float(h2));
            v3 = __float2bfloat16_rn(f3 - __bfloat162float(h3));
        }
        g_Bfrag[sk][n][ln] = make_uint2(pack_bf16x2(v0, v1), pack_bf16x2(v2, v3));
    }
}

__global__ __launch_bounds__(THREADS, 3)
void afm_kernel(const float* __restrict__ x,
                const float* __restrict__ b1,
                const float* __restrict__ w2,
                const float* __restrict__ fcw,
                const float* __restrict__ fcb,
                float* __restrict__ out)
{
    extern __shared__ __align__(16) char smem_raw[];
    Smem* S = (Smem*)smem_raw;
    uint32_t Abase;
    asm("{ .reg .u64 t; cvta.to.shared.u64 t, %1; cvt.u32.u64 %0, t; }"
        : "=r"(Abase) : "l"(S->A));

    const int tid  = threadIdx.x;
    const int b    = blockIdx.x;
    const int lane = tid & 31;
    const int warp = tid >> 5;

    // ---- cooperative loads ----
    const float* xb = x + (size_t)b * (NF * EMB);
    for (int idx = tid; idx < NF * EMB; idx += THREADS)
        S->Xs[(idx >> 6) * XPAD + (idx & 63)] = xb[idx];

    if (tid < EMB) {
        S->z[2 * tid] = b1[tid];
        S->z[2 * tid + 1] = w2[tid];
        S->fcw[tid] = fcw[tid];
    }

    // copy precomputed B fragments (gmem -> smem, L2-resident after wave 1)
    {
        const uint4* src = (const uint4*)g_Bfrag;
        uint4* dst = (uint4*)S->Bfrag;
        #pragma unroll
        for (int i = 0; i < 4; i++) dst[tid + i * THREADS] = src[tid + i * THREADS];
    }

    // pair offsets via closed-form triu index: row i starts at i*(63-i)/2
    for (int p = tid; p < NPAIR; p += THREADS) {
        float t = sqrtf((float)(3969 - 8 * p));
        int i = (int)((63.0f - t) * 0.5f);
        while ((i + 1) * (63 - (i + 1)) / 2 <= p) i++;   // <=2 fixup steps
        while (i * (63 - i) / 2 > p) i--;
        int j = i + 1 + (p - i * (63 - i) / 2);
        S->offs[p] = (uint32_t)(i * XPAD) | ((uint32_t)(j * XPAD) << 16);
    }
    __syncthreads();

    // ---- four quarters of 128 pair-rows ----
    for (int qt = 0; qt < NQ; qt++) {
        // build A quarter: row r, cols 0-63 = hi(C), 64-127 = lo(C)
        for (int idx = tid; idx < MH * 16; idx += THREADS) {
            int ch = idx & 15, r = idx >> 4;
            int p = qt * MH + r;
            char* row = S->A + r * ABYTES_ROW;
            if (p < NPAIR) {
                uint32_t o = S->offs[p];
                const float* xi = S->Xs + (o & 0xFFFFu) + 4 * ch;
                const float* xj = S->Xs + (o >> 16) + 4 * ch;
                float4 a4 = *(const float4*)xi;
                float4 c4 = *(const float4*)xj;
                float c0 = a4.x * c4.x, c1 = a4.y * c4.y, c2 = a4.z * c4.z, c3 = a4.w * c4.w;
                uint32_t hi01 = cvt2_bf16(c0, c1);
                uint32_t hi23 = cvt2_bf16(c2, c3);
                // widen rounded hi back to f32 via bit ops
                float r0 = __uint_as_float(hi01 << 16);
                float r1 = __uint_as_float(hi01 & 0xFFFF0000u);
                float r2 = __uint_as_float(hi23 << 16);
                float r3 = __uint_as_float(hi23 & 0xFFFF0000u);
                uint32_t lo01 = cvt2_bf16(c0 - r0, c1 - r1);
                uint32_t lo23 = cvt2_bf16(c2 - r2, c3 - r3);
                *(uint2*)(row + 8 * ch)       = make_uint2(hi01, hi23);
                *(uint2*)(row + 128 + 8 * ch) = make_uint2(lo01, lo23);
            } else {
                *(uint2*)(row + 8 * ch)       = make_uint2(0u, 0u);
                *(uint2*)(row + 128 + 8 * ch) = make_uint2(0u, 0u);
            }
        }
        __syncthreads();

        // MMA: warp owns one 16-row m-tile: rows [16*warp, 16*warp+16)
        const int rb = warp * 16;
        const int c = lane & 3, g = lane >> 2;
        float ps0 = 0.f, ps1 = 0.f;

        #pragma unroll
        for (int ng = 0; ng < 2; ng++) {
            float d[4][4];
            #pragma unroll
            for (int n4 = 0; n4 < 4; n4++)
                #pragma unroll
                for (int q = 0; q < 4; q++) d[n4][q] = 0.f;

            #pragma unroll
            for (int ks = 0; ks < 4; ks++) {
                uint32_t ah[4], al[4];
                lda(ah, Abase, rb, 16 * ks, lane);        // A_hi
                lda(al, Abase, rb, 64 + 16 * ks, lane);   // A_lo
                #pragma unroll
                for (int n4 = 0; n4 < 4; n4++) {
                    int n = ng * 4 + n4;
                    uint2 bh = S->Bfrag[ks][n][lane];
                    uint2 bl = S->Bfrag[4 + ks][n][lane];
                    mma16816(d[n4], ah, bh);   // C_hi * W_hi
                    mma16816(d[n4], ah, bl);   // C_hi * W_lo
                    mma16816(d[n4], al, bh);   // C_lo * W_hi
                }
            }

            // fold this n-group into partial scores
            #pragma unroll
            for (int n4 = 0; n4 < 4; n4++) {
                int n = ng * 4 + n4;
                float4 zz = *(const float4*)&S->z[2 * (8 * n + 2 * c)];  // b1/w2 for 2 cols
                ps0 += fmaxf(d[n4][0] + zz.x, 0.f) * zz.y
                     + fmaxf(d[n4][1] + zz.z, 0.f) * zz.w;
                ps1 += fmaxf(d[n4][2] + zz.x, 0.f) * zz.y
                     + fmaxf(d[n4][3] + zz.z, 0.f) * zz.w;
            }
        }

        #pragma unroll
        for (int off = 1; off <= 2; off <<= 1) {
            ps0 += __shfl_xor_sync(0xFFFFFFFFu, ps0, off);
            ps1 += __shfl_xor_sync(0xFFFFFFFFu, ps1, off);
        }
        if (c == 0) {
            int p0 = qt * MH + rb + g;
            if (p0 < NPAIR)     S->score[p0]     = ps0;
            if (p0 + 8 < NPAIR) S->score[p0 + 8] = ps1;
        }
        __syncthreads();   // A consumed by all warps; safe to rebuild
    }

    // ---- softmax over 496 pairs ----
    float m = -INFINITY;
    for (int p = tid; p < NPAIR; p += THREADS) m = fmaxf(m, S->score[p]);
    #pragma unroll
    for (int o = 16; o; o >>= 1) m = fmaxf(m, __shfl_xor_sync(0xFFFFFFFFu, m, o));
    if (lane == 0) S->red[warp] = m;
    __syncthreads();
    if (tid == 0) {
        float mm = S->red[0];
        #pragma unroll
        for (int k = 1; k < 8; k++) mm = fmaxf(mm, S->red[k]);
        S->smax = mm;
    }
    __syncthreads();
    const float mm = S->smax;

    float lsum = 0.f;
    for (int p = tid; p < NPAIR; p += THREADS) {
        float e = __expf(S->score[p] - mm);
        S->score[p] = e;
        lsum += e;
    }
    #pragma unroll
    for (int o = 16; o; o >>= 1) lsum += __shfl_xor_sync(0xFFFFFFFFu, lsum, o);
    if (lane == 0) S->red[warp] = lsum;
    __syncthreads();
    if (tid == 0) {
        float ss = 0.f;
        #pragma unroll
        for (int k = 0; k < 8; k++) ss += S->red[k];
        S->sinv = 1.0f / ss;
    }
    __syncthreads();
    const float inv = S->sinv;

    // ---- phase 2: f[d] = sum_p attn_p * x_i[d]*x_j[d]; y = f.fc_w + fc_b ----
    {
        const int dg = tid & 15;        // dim group: dims [4dg, 4dg+4)
        const int pg = tid >> 4;        // 16 pair groups
        float4 acc = make_float4(0.f, 0.f, 0.f, 0.f);
        for (int p = pg; p < NPAIR; p += 16) {
            float s = S->score[p];
            uint32_t o = S->offs[p];
            float4 xi = *(const float4*)(S->Xs + (o & 0xFFFFu) + 4 * dg);
            float4 xj = *(const float4*)(S->Xs + (o >> 16) + 4 * dg);
            acc.x += s * (xi.x * xj.x);
            acc.y += s * (xi.y * xj.y);
            acc.z += s * (xi.z * xj.z);
            acc.w += s * (xi.w * xj.w);
        }
        *(float4*)(S->fp + pg * EMB + 4 * dg) = acc;
    }
    __syncthreads();
    if (tid < EMB) {
        float f = 0.f;
        #pragma unroll
        for (int pg = 0; pg < 16; pg++) f += S->fp[pg * EMB + tid];
        S->fp[tid] = f * inv * S->fcw[tid];
    }
    __syncthreads();
    if (tid == 0) {
        float y = fcb[0];
        #pragma unroll
        for (int k = 0; k < EMB; k++) y += S->fp[k];
        out[b] = y;
    }
}

extern "C" void kernel_launch(void* const* d_in, const int* in_sizes, int n_in,
                              void* d_out, int out_size)
{
    const float* x   = (const float*)d_in[0];
    const float* w1  = (const float*)d_in[1];
    const float* b1  = (const float*)d_in[2];
    const float* w2  = (const float*)d_in[3];
    const float* fcw = (const float*)d_in[4];
    const float* fcb = (const float*)d_in[5];
    float* out = (float*)d_out;

    static int smem_set = -1;
    const int smem_bytes = (int)sizeof(Smem);
    if (smem_set != smem_bytes) {
        cudaFuncSetAttribute(afm_kernel, cudaFuncAttributeMaxDynamicSharedMemorySize, smem_bytes);
        smem_set = smem_bytes;
    }

    const int batch = out_size;   // NUM_CLASSES = 1
    bfrag_prep<<<1, 256>>>(w1);                                      // batch-invariant B fragments
    afm_kernel<<<batch, THREADS, smem_bytes>>>(x, b1, w2, fcw, fcb, out);
}

// round 14
// speedup vs baseline: 3.6239x; 1.1346x over previous
#include <cuda_runtime.h>
#include <cuda_bf16.h>
#include <cstdint>
#include <math.h>

// AFM: y[b] = fc_b + fc_w . sum_p softmax_p( w2 . relu(W1^T (x_i*x_j) + b1) ) * (x_i*x_j)
// One CTA per batch row.
// R14: R13 with the ldmatrix alignment bug fixed: S row stride 34 elem (68 B, rows
//      only 4B-aligned -> "misaligned address") changed to 40 elem (80 B, 16B-aligned).
//   - flat n-loop (ng split removed): A fragments loaded once per ks -> ldmatrix wf halved.
//   - phase-2 as f = 0.5*diag(X^T (S X)) on tensor cores (split-bf16 3-product).

#define NF      32
#define EMB     64
#define NPAIR   496
#define XPAD    68
#define THREADS 256
#define MH      128            // rows per quarter
#define NQ      4
#define ABYTES_ROW 272         // 136 bf16: 16B-aligned, 4-bank offset per row

// phase-2 structures inside the A region (valid after last quarter)
#define SROW     40            // S row stride in elements (80 B, multiple of 16B for ldmatrix)
#define SH_OFF   0             // uint16 Sh[32][40]  (2560 B)
#define SL_OFF   2560          // uint16 Sl[32][40]  (2560 B)
#define XFH_OFF  5120          // uint2  Xfh[2][8][32] (4096 B)
#define XFL_OFF  9216          // uint2  Xfl[2][8][32] (4096 B)

__device__ uint2 g_Bfrag[8][8][32];   // [src*4+ks][ntile][lane]; src0=W_hi, src1=W_lo

struct Smem {
    char  A[MH * ABYTES_ROW];        // 34816  A quarter | phase-2 region (Sh/Sl/Xfrag)
    uint2 Bfrag[8][8][32];           // 16384
    float Xs[NF * XPAD];             // 8704
    float z[2 * EMB];                // (b1[a], w2[a]) interleaved
    float score[NPAIR];              // 1984
    uint32_t offs[NPAIR];            // 1984   (ci*XPAD) | (cj*XPAD)<<16  (word offsets)
    float fcw[EMB];
    float fp2[2 * EMB];              // 512    phase-2 partials (per mi-half)
    float red[8];
    float smax, sinv;
};

__device__ __forceinline__ uint32_t pack_bf16x2(__nv_bfloat16 l, __nv_bfloat16 h) {
    return (uint32_t)__bfloat16_as_ushort(l) | ((uint32_t)__bfloat16_as_ushort(h) << 16);
}

// packed pair (lo=a, hi=b) -> bf16x2 in one cvt
__device__ __forceinline__ uint32_t cvt2_bf16(float lo, float hi) {
    uint32_t r;
    asm("cvt.rn.bf16x2.f32 %0, %1, %2;" : "=r"(r) : "f"(hi), "f"(lo));
    return r;
}

__device__ __forceinline__ void mma16816(float* d, const uint32_t* a, uint2 b) {
    asm volatile(
        "mma.sync.aligned.m16n8k16.row.col.f32.bf16.bf16.f32 "
        "{%0,%1,%2,%3}, {%4,%5,%6,%7}, {%8,%9}, {%0,%1,%2,%3};"
        : "+f"(d[0]), "+f"(d[1]), "+f"(d[2]), "+f"(d[3])
        : "r"(a[0]), "r"(a[1]), "r"(a[2]), "r"(a[3]), "r"(b.x), "r"(b.y));
}

// A fragment (m16k16) from the C buffer, row stride ABYTES_ROW
__device__ __forceinline__ void lda(uint32_t* a, uint32_t Abase, int rbase, int k0, int lane) {
    int mat = lane >> 3, r8 = lane & 7;
    int row = rbase + r8 + ((mat & 1) << 3);
    int col = k0 + ((mat >> 1) << 3);
    uint32_t addr = Abase + (uint32_t)(row * ABYTES_ROW + col * 2);
    asm volatile("ldmatrix.sync.aligned.m8n8.x4.shared.b16 {%0,%1,%2,%3}, [%4];"
                 : "=r"(a[0]), "=r"(a[1]), "=r"(a[2]), "=r"(a[3]) : "r"(addr));
}

// A fragment (m16k16) from the S matrix, row stride SROW*2 = 80 B (16B-aligned rows)
__device__ __forceinline__ void lda_s(uint32_t* a, uint32_t Sbase, int mi, int ks, int lane) {
    int mat = lane >> 3, r8 = lane & 7;
    int row = 16 * mi + r8 + ((mat & 1) << 3);
    int col = 16 * ks + ((mat >> 1) << 3);
    uint32_t addr = Sbase + (uint32_t)(row * (SROW * 2) + col * 2);
    asm volatile("ldmatrix.sync.aligned.m8n8.x4.shared.b16 {%0,%1,%2,%3}, [%4];"
                 : "=r"(a[0]), "=r"(a[1]), "=r"(a[2]), "=r"(a[3]) : "r"(addr));
}

// ---- one-time chip-wide B-fragment build (batch-invariant) ----
__global__ void bfrag_prep(const float* __restrict__ w1) {
    int tid = threadIdx.x;
    for (int e = tid; e < 8 * 8 * 32; e += 256) {
        int ln = e & 31, n = (e >> 5) & 7, sk = e >> 8;   // sk = src*4 + ks4
        int src = sk >> 2, k4 = sk & 3;
        int c = ln & 3, g = ln >> 2;
        int a = n * 8 + g;
        int d0 = k4 * 16 + 2 * c;
        float f0 = w1[(d0)     * EMB + a];
        float f1 = w1[(d0 + 1) * EMB + a];
        float f2 = w1[(d0 + 8) * EMB + a];
        float f3 = w1[(d0 + 9) * EMB + a];
        __nv_bfloat16 h0 = __float2bfloat16_rn(f0), h1 = __float2bfloat16_rn(f1);
        __nv_bfloat16 h2 = __float2bfloat16_rn(f2), h3 = __float2bfloat16_rn(f3);
        __nv_bfloat16 v0, v1, v2, v3;
        if (src == 0) { v0 = h0; v1 = h1; v2 = h2; v3 = h3; }
        else {
            v0 = __float2bfloat16_rn(f0 - __bfloat162float(h0));
            v1 = __float2bfloat16_rn(f1 - __bfloat162float(h1));
            v2 = __float2bfloat16_rn(f2 - __bfloat162float(h2));
            v3 = __float2bfloat16_rn(f3 - __bfloat162float(h3));
        }
        g_Bfrag[sk][n][ln] = make_uint2(pack_bf16x2(v0, v1), pack_bf16x2(v2, v3));
    }
}

__global__ __launch_bounds__(THREADS, 3)
void afm_kernel(const float* __restrict__ x,
                const float* __restrict__ b1,
                const float* __restrict__ w2,
                const float* __restrict__ fcw,
                const float* __restrict__ fcb,
                float* __restrict__ out)
{
    extern __shared__ __align__(16) char smem_raw[];
    Smem* S = (Smem*)smem_raw;
    uint32_t Abase;
    asm("{ .reg .u64 t; cvta.to.shared.u64 t, %1; cvt.u32.u64 %0, t; }"
        : "=r"(Abase) : "l"(S->A));

    const int tid  = threadIdx.x;
    const int b    = blockIdx.x;
    const int lane = tid & 31;
    const int warp = tid >> 5;

    // ---- cooperative loads ----
    const float* xb = x + (size_t)b * (NF * EMB);
    for (int idx = tid; idx < NF * EMB; idx += THREADS)
        S->Xs[(idx >> 6) * XPAD + (idx & 63)] = xb[idx];

    if (tid < EMB) {
        S->z[2 * tid] = b1[tid];
        S->z[2 * tid + 1] = w2[tid];
        S->fcw[tid] = fcw[tid];
    }

    // copy precomputed B fragments (gmem -> smem, L2-resident after wave 1)
    {
        const uint2* src = (const uint2*)g_Bfrag;
        uint2* dst = (uint2*)S->Bfrag;
        #pragma unroll
        for (int i = 0; i < 8; i++) dst[tid + i * THREADS] = src[tid + i * THREADS];
    }

    // pair offsets via closed-form triu index: row i starts at i*(63-i)/2
    for (int p = tid; p < NPAIR; p += THREADS) {
        float t = sqrtf((float)(3969 - 8 * p));
        int i = (int)((63.0f - t) * 0.5f);
        while ((i + 1) * (63 - (i + 1)) / 2 <= p) i++;   // <=2 fixup steps
        while (i * (63 - i) / 2 > p) i--;
        int j = i + 1 + (p - i * (63 - i) / 2);
        S->offs[p] = (uint32_t)(i * XPAD) | ((uint32_t)(j * XPAD) << 16);
    }
    __syncthreads();

    // ---- four quarters of 128 pair-rows ----
    for (int qt = 0; qt < NQ; qt++) {
        // build A quarter: row r, cols 0-63 = hi(C), 64-127 = lo(C)
        for (int idx = tid; idx < MH * 16; idx += THREADS) {
            int ch = idx & 15, r = idx >> 4;
            int p = qt * MH + r;
            char* row = S->A + r * ABYTES_ROW;
            if (p < NPAIR) {
                uint32_t o = S->offs[p];
                const float* xi = S->Xs + (o & 0xFFFFu) + 4 * ch;
                const float* xj = S->Xs + (o >> 16) + 4 * ch;
                float4 a4 = *(const float4*)xi;
                float4 c4 = *(const float4*)xj;
                float c0 = a4.x * c4.x, c1 = a4.y * c4.y, c2 = a4.z * c4.z, c3 = a4.w * c4.w;
                uint32_t hi01 = cvt2_bf16(c0, c1);
                uint32_t hi23 = cvt2_bf16(c2, c3);
                float r0 = __uint_as_float(hi01 << 16);
                float r1 = __uint_as_float(hi01 & 0xFFFF0000u);
                float r2 = __uint_as_float(hi23 << 16);
                float r3 = __uint_as_float(hi23 & 0xFFFF0000u);
                uint32_t lo01 = cvt2_bf16(c0 - r0, c1 - r1);
                uint32_t lo23 = cvt2_bf16(c2 - r2, c3 - r3);
                *(uint2*)(row + 8 * ch)       = make_uint2(hi01, hi23);
                *(uint2*)(row + 128 + 8 * ch) = make_uint2(lo01, lo23);
            } else {
                *(uint2*)(row + 8 * ch)       = make_uint2(0u, 0u);
                *(uint2*)(row + 128 + 8 * ch) = make_uint2(0u, 0u);
            }
        }
        __syncthreads();

        // MMA: warp owns one 16-row m-tile, flat n 0..7
        const int rb = warp * 16;
        const int c = lane & 3, g = lane >> 2;
        float d[8][4];
        #pragma unroll
        for (int n = 0; n < 8; n++)
            #pragma unroll
            for (int q = 0; q < 4; q++) d[n][q] = 0.f;

        #pragma unroll
        for (int ks = 0; ks < 4; ks++) {
            uint32_t ah[4], al[4];
            lda(ah, Abase, rb, 16 * ks, lane);        // A_hi
            lda(al, Abase, rb, 64 + 16 * ks, lane);   // A_lo
            #pragma unroll
            for (int n = 0; n < 8; n++) {
                uint2 bh = S->Bfrag[ks][n][lane];
                uint2 bl = S->Bfrag[4 + ks][n][lane];
                mma16816(d[n], ah, bh);   // C_hi * W_hi
                mma16816(d[n], ah, bl);   // C_hi * W_lo
                mma16816(d[n], al, bh);   // C_lo * W_hi
            }
        }

        float ps0 = 0.f, ps1 = 0.f;
        #pragma unroll
        for (int n = 0; n < 8; n++) {
            float4 zz = *(const float4*)&S->z[2 * (8 * n + 2 * c)];  // b1/w2 for 2 cols
            ps0 += fmaxf(d[n][0] + zz.x, 0.f) * zz.y
                 + fmaxf(d[n][1] + zz.z, 0.f) * zz.w;
            ps1 += fmaxf(d[n][2] + zz.x, 0.f) * zz.y
                 + fmaxf(d[n][3] + zz.z, 0.f) * zz.w;
        }

        #pragma unroll
        for (int off = 1; off <= 2; off <<= 1) {
            ps0 += __shfl_xor_sync(0xFFFFFFFFu, ps0, off);
            ps1 += __shfl_xor_sync(0xFFFFFFFFu, ps1, off);
        }
        if (c == 0) {
            int p0 = qt * MH + rb + g;
            if (p0 < NPAIR)     S->score[p0]     = ps0;
            if (p0 + 8 < NPAIR) S->score[p0 + 8] = ps1;
        }
        __syncthreads();   // A consumed by all warps; safe to rebuild
    }

    // ---- softmax over 496 pairs ----
    float m = -INFINITY;
    for (int p = tid; p < NPAIR; p += THREADS) m = fmaxf(m, S->score[p]);
    #pragma unroll
    for (int o = 16; o; o >>= 1) m = fmaxf(m, __shfl_xor_sync(0xFFFFFFFFu, m, o));
    if (lane == 0) S->red[warp] = m;
    __syncthreads();
    if (tid == 0) {
        float mm = S->red[0];
        #pragma unroll
        for (int k = 1; k < 8; k++) mm = fmaxf(mm, S->red[k]);
        S->smax = mm;
    }
    __syncthreads();
    const float mm = S->smax;

    float lsum = 0.f;
    for (int p = tid; p < NPAIR; p += THREADS) {
        float e = __expf(S->score[p] - mm);
        S->score[p] = e;
        lsum += e;
    }
    #pragma unroll
    for (int o = 16; o; o >>= 1) lsum += __shfl_xor_sync(0xFFFFFFFFu, lsum, o);
    if (lane == 0) S->red[warp] = lsum;
    __syncthreads();
    if (tid == 0) {
        float ss = 0.f;
        #pragma unroll
        for (int k = 0; k < 8; k++) ss += S->red[k];
        S->sinv = 1.0f / ss;
    }
    __syncthreads();
    const float inv = S->sinv;

    // ---- phase 2: f = 0.5 * diag(X^T (S X)),  T = S X via 3-product bf16 MMA ----
    uint16_t* Sh = (uint16_t*)(S->A + SH_OFF);
    uint16_t* Sl = (uint16_t*)(S->A + SL_OFF);
    uint2 (*Xfh)[8][32] = (uint2 (*)[8][32])(S->A + XFH_OFF);
    uint2 (*Xfl)[8][32] = (uint2 (*)[8][32])(S->A + XFL_OFF);

    // zero S diagonal; padding cols (32..39) never read by lda_s (ks<=1 -> cols<32)
    if (tid < NF) { Sh[tid * SROW + tid] = 0; Sl[tid * SROW + tid] = 0; }

    // scatter exp-scores into symmetric S (hi/lo bf16)
    for (int p = tid; p < NPAIR; p += THREADS) {
        float s = S->score[p];
        uint32_t o = S->offs[p];
        int i = (int)(o & 0xFFFFu) / XPAD;
        int j = (int)(o >> 16) / XPAD;
        __nv_bfloat16 hb = __float2bfloat16_rn(s);
        float hf = __bfloat162float(hb);
        __nv_bfloat16 lb = __float2bfloat16_rn(s - hf);
        uint16_t hu = __bfloat16_as_ushort(hb), lu = __bfloat16_as_ushort(lb);
        Sh[i * SROW + j] = hu; Sh[j * SROW + i] = hu;
        Sl[i * SROW + j] = lu; Sl[j * SROW + i] = lu;
    }

    // build X fragments (B operand of m16n8k16): lane t -> n_col = 8n+(t>>2), k rows j0=16ks+2(t&3)
    for (int e = tid; e < 2 * 8 * 32; e += THREADS) {
        int t = e & 31, n = (e >> 5) & 7, ks = e >> 8;
        int dcol = 8 * n + (t >> 2);
        int j0 = 16 * ks + 2 * (t & 3);
        float v00 = S->Xs[j0 * XPAD + dcol];
        float v01 = S->Xs[(j0 + 1) * XPAD + dcol];
        float v10 = S->Xs[(j0 + 8) * XPAD + dcol];
        float v11 = S->Xs[(j0 + 9) * XPAD + dcol];
        uint32_t h0 = cvt2_bf16(v00, v01);
        uint32_t h1 = cvt2_bf16(v10, v11);
        float r00 = __uint_as_float(h0 << 16), r01 = __uint_as_float(h0 & 0xFFFF0000u);
        float r10 = __uint_as_float(h1 << 16), r11 = __uint_as_float(h1 & 0xFFFF0000u);
        Xfh[ks][n][t] = make_uint2(h0, h1);
        Xfl[ks][n][t] = make_uint2(cvt2_bf16(v00 - r00, v01 - r01),
                                   cvt2_bf16(v10 - r10, v11 - r11));
    }
    __syncthreads();

    // T = S X: warp w -> mi = w&1 (rows 16mi..+16), n-tiles {w>>1, (w>>1)+4}
    {
        const int mi = warp & 1, nb = warp >> 1;
        const int c = lane & 3, g = lane >> 2;
        uint32_t sh[2][4], sl[2][4];
        uint32_t ShB = Abase + SH_OFF, SlB = Abase + SL_OFF;
        lda_s(sh[0], ShB, mi, 0, lane); lda_s(sh[1], ShB, mi, 1, lane);
        lda_s(sl[0], SlB, mi, 0, lane); lda_s(sl[1], SlB, mi, 1, lane);

        #pragma unroll
        for (int u = 0; u < 2; u++) {
            int n = nb + 4 * u;
            float t[4] = {0.f, 0.f, 0.f, 0.f};
            #pragma unroll
            for (int ks = 0; ks < 2; ks++) {
                uint2 bh = Xfh[ks][n][lane];
                uint2 bl = Xfl[ks][n][lane];
                mma16816(t, sh[ks], bh);   // S_hi * X_hi
                mma16816(t, sl[ks], bh);   // S_lo * X_hi
                mma16816(t, sh[ks], bl);   // S_hi * X_lo
            }
            // fold: partial_d = sum_i X[i][d] * T[i][d] over this warp's rows
            int i0 = 16 * mi + g, i1 = i0 + 8;
            int d0 = 8 * n + 2 * c, d1 = d0 + 1;
            float p0 = S->Xs[i0 * XPAD + d0] * t[0] + S->Xs[i1 * XPAD + d0] * t[2];
            float p1 = S->Xs[i0 * XPAD + d1] * t[1] + S->Xs[i1 * XPAD + d1] * t[3];
            #pragma unroll
            for (int off = 4; off <= 16; off <<= 1) {     // reduce over g (lane bits 2-4)
                p0 += __shfl_xor_sync(0xFFFFFFFFu, p0, off);
                p1 += __shfl_xor_sync(0xFFFFFFFFu, p1, off);
            }
            if (g == 0) {
                S->fp2[mi * EMB + d0] = p0;
                S->fp2[mi * EMB + d1] = p1;
            }
        }
    }
    __syncthreads();

    if (tid < EMB) {
        float f = (S->fp2[tid] + S->fp2[EMB + tid]) * 0.5f * inv * S->fcw[tid];
        S->fp2[tid] = f;
    }
    __syncthreads();
    if (tid == 0) {
        float y = fcb[0];
        #pragma unroll
        for (int k = 0; k < EMB; k++) y += S->fp2[k];
        out[b] = y;
    }
}

extern "C" void kernel_launch(void* const* d_in, const int* in_sizes, int n_in,
                              void* d_out, int out_size)
{
    const float* x   = (const float*)d_in[0];
    const float* w1  = (const float*)d_in[1];
    const float* b1  = (const float*)d_in[2];
    const float* w2  = (const float*)d_in[3];
    const float* fcw = (const float*)d_in[4];
    const float* fcb = (const float*)d_in[5];
    float* out = (float*)d_out;

    static int smem_set = -1;
    const int smem_bytes = (int)sizeof(Smem);
    if (smem_set != smem_bytes) {
        cudaFuncSetAttribute(afm_kernel, cudaFuncAttributeMaxDynamicSharedMemorySize, smem_bytes);
        smem_set = smem_bytes;
    }

    const int batch = out_size;   // NUM_CLASSES = 1
    bfrag_prep<<<1, 256>>>(w1);                                      // batch-invariant B fragments
    afm_kernel<<<batch, THREADS, smem_bytes>>>(x, b1, w2, fcw, fcb, out);
}